// round 1
// baseline (speedup 1.0000x reference)
#include <cuda_runtime.h>
#include <cstdint>
#include <cstddef>

#define NN 100000
#define EE 1600000
#define HF 128
#define KIN 512
#define NBLK 98   // ceil(NN/1024)

// ---------------- scratch (static device globals; no allocations) ----------------
__device__ int   g_is64;
__device__ float g_invnorm[NN];
__device__ int   g_cnt[NN];
__device__ float g_dinv[NN];
__device__ int   g_erow[EE];
__device__ int   g_ecol0[EE];
__device__ int   g_off[NN + 1];
__device__ int   g_cursor[NN];
__device__ int   g_bsum[128];
__device__ int   g_boff[128];
__device__ int   g_ecol[EE];
__device__ float g_ew[EE];
__device__ float g_h [(size_t)NN * HF];
__device__ float g_za[(size_t)NN * HF];
__device__ float g_zb[(size_t)NN * HF];
__device__ float g_cat[(size_t)NN * 4 * HF];

// ---------------- edge index width detection (int64 vs int32) ----------------
__global__ void k_detect(const void* ei) {
    const unsigned int* p = (const unsigned int*)ei;
    int ok64 = 1;
    for (int i = threadIdx.x; i < 64; i += 32)
        if (p[2 * i + 1] != 0u) ok64 = 0;
    ok64 = __all_sync(0xffffffffu, ok64);
    if (threadIdx.x == 0) g_is64 = ok64;
}

__global__ void k_init_cnt() {
    int i = blockIdx.x * blockDim.x + threadIdx.x;
    if (i < NN) g_cnt[i] = 0;
}

// row-norm of features: invnorm[i] = 1 / max(||feats[i]||, 1e-12)
__global__ void k_invnorm(const float* __restrict__ feats) {
    int w = (blockIdx.x * blockDim.x + threadIdx.x) >> 5;
    int lane = threadIdx.x & 31;
    if (w >= NN) return;
    const float4* p = (const float4*)(feats + (size_t)w * KIN);
    float ss = 0.f;
#pragma unroll
    for (int i = 0; i < 4; ++i) {
        float4 v = p[i * 32 + lane];
        ss += v.x * v.x + v.y * v.y + v.z * v.z + v.w * v.w;
    }
#pragma unroll
    for (int o = 16; o > 0; o >>= 1) ss += __shfl_xor_sync(0xffffffffu, ss, o);
    if (lane == 0) g_invnorm[w] = 1.0f / fmaxf(sqrtf(ss), 1e-12f);
}

// convert edges to int32 + count out-degree (rows)
__global__ void k_count(const void* ei) {
    int e = blockIdx.x * blockDim.x + threadIdx.x;
    if (e >= EE) return;
    int r, c;
    if (g_is64) {
        const long long* p = (const long long*)ei;
        r = (int)p[e]; c = (int)p[EE + e];
    } else {
        const int* p = (const int*)ei;
        r = p[e]; c = p[EE + e];
    }
    g_erow[e] = r;
    g_ecol0[e] = c;
    atomicAdd(&g_cnt[r], 1);
}

// exclusive scan of g_cnt -> g_off (3 kernels, block size 1024)
__global__ void k_scan1() {
    __shared__ int sm[1024];
    int t = threadIdx.x;
    int i = blockIdx.x * 1024 + t;
    int v = (i < NN) ? g_cnt[i] : 0;
    sm[t] = v;
    __syncthreads();
    for (int d = 1; d < 1024; d <<= 1) {
        int add = (t >= d) ? sm[t - d] : 0;
        __syncthreads();
        sm[t] += add;
        __syncthreads();
    }
    int incl = sm[t];
    if (i < NN) g_off[i] = incl - v;
    if (t == 1023) g_bsum[blockIdx.x] = incl;
}

__global__ void k_scan2() {
    __shared__ int sm[128];
    int t = threadIdx.x;
    int v = (t < NBLK) ? g_bsum[t] : 0;
    sm[t] = v;
    __syncthreads();
    for (int d = 1; d < 128; d <<= 1) {
        int add = (t >= d) ? sm[t - d] : 0;
        __syncthreads();
        sm[t] += add;
        __syncthreads();
    }
    g_boff[t] = sm[t] - v;
}

__global__ void k_scan3() {
    int t = threadIdx.x;
    int i = blockIdx.x * 1024 + t;
    if (i < NN) {
        int off = g_off[i] + g_boff[blockIdx.x];
        g_off[i] = off;
        g_cursor[i] = off;
        g_dinv[i] = rsqrtf((float)(g_cnt[i] + 1));   // +1 for self loop
        if (i == 0) g_off[NN] = EE;
    }
}

__global__ void k_scatter() {
    int e = blockIdx.x * blockDim.x + threadIdx.x;
    if (e >= EE) return;
    int r = g_erow[e], c = g_ecol0[e];
    int pos = atomicAdd(&g_cursor[r], 1);
    g_ecol[pos] = c;
    g_ew[pos] = g_dinv[r] * g_dinv[c];
}

// warp-per-node SpMM with self-loop, CSR, register accumulation (no atomics)
__global__ void k_spmm(const float* __restrict__ zin, float* __restrict__ zout) {
    int w = (blockIdx.x * blockDim.x + threadIdx.x) >> 5;
    int lane = threadIdx.x & 31;
    if (w >= NN) return;
    int s = g_off[w], e = g_off[w + 1];
    float dn = g_dinv[w];
    float ws = dn * dn;
    float4 acc = ((const float4*)(zin + (size_t)w * HF))[lane];
    acc.x *= ws; acc.y *= ws; acc.z *= ws; acc.w *= ws;
#pragma unroll 4
    for (int j = s; j < e; ++j) {
        int c = g_ecol[j];
        float wt = g_ew[j];
        float4 v = ((const float4*)(zin + (size_t)c * HF))[lane];
        acc.x += wt * v.x; acc.y += wt * v.y; acc.z += wt * v.z; acc.w += wt * v.w;
    }
    ((float4*)(zout + (size_t)w * HF))[lane] = acc;
}

// ---------------- fused GEMM + bias + LayerNorm + ReLU ----------------
// C[m, noff + n] = relu(LN(A[m,:K] (*rowscale[m]) @ B[K,128] + bias) * gamma + beta)
template <int K>
__global__ __launch_bounds__(256, 2)
void k_gemm(const float* __restrict__ A, int lda, const float* __restrict__ rowscale,
            const float* __restrict__ B,
            const float* __restrict__ bias, const float* __restrict__ gamma,
            const float* __restrict__ beta,
            float* __restrict__ C, int ldc, int noff)
{
    __shared__ float As[16][128];
    __shared__ float Bs[16][128];
    int m0 = blockIdx.x * 128;
    int t = threadIdx.x;
    int tx = t & 15, ty = t >> 4;

    float acc[8][8];
#pragma unroll
    for (int i = 0; i < 8; ++i)
#pragma unroll
        for (int j = 0; j < 8; ++j) acc[i][j] = 0.f;

    for (int k0 = 0; k0 < K; k0 += 16) {
        // A tile -> smem (k-major), with optional per-row scale
#pragma unroll
        for (int it = 0; it < 2; ++it) {
            int f = t + it * 256;
            int row = f >> 2, kq = (f & 3) * 4;
            int gm = m0 + row;
            float4 av = make_float4(0.f, 0.f, 0.f, 0.f);
            if (gm < NN) {
                av = *(const float4*)(A + (size_t)gm * lda + k0 + kq);
                if (rowscale) {
                    float sc = rowscale[gm];
                    av.x *= sc; av.y *= sc; av.z *= sc; av.w *= sc;
                }
            }
            As[kq + 0][row] = av.x;
            As[kq + 1][row] = av.y;
            As[kq + 2][row] = av.z;
            As[kq + 3][row] = av.w;
        }
        // B tile -> smem
#pragma unroll
        for (int it = 0; it < 2; ++it) {
            int f = t + it * 256;
            int kk = f >> 5, n4 = (f & 31) * 4;
            *(float4*)&Bs[kk][n4] = *(const float4*)(B + (size_t)(k0 + kk) * HF + n4);
        }
        __syncthreads();
#pragma unroll
        for (int kk = 0; kk < 16; ++kk) {
            float a[8], b[8];
            *(float4*)&a[0] = *(const float4*)&As[kk][ty * 8];
            *(float4*)&a[4] = *(const float4*)&As[kk][ty * 8 + 4];
            *(float4*)&b[0] = *(const float4*)&Bs[kk][tx * 8];
            *(float4*)&b[4] = *(const float4*)&Bs[kk][tx * 8 + 4];
#pragma unroll
            for (int i = 0; i < 8; ++i)
#pragma unroll
                for (int j = 0; j < 8; ++j) acc[i][j] += a[i] * b[j];
        }
        __syncthreads();
    }

    // epilogue: bias, LN over the 128-wide row (16 tx threads = one half-warp), relu
    float bb[8], gg[8], ee[8];
#pragma unroll
    for (int j = 0; j < 8; ++j) {
        int c = tx * 8 + j;
        bb[j] = bias[c]; gg[j] = gamma[c]; ee[j] = beta[c];
    }
#pragma unroll
    for (int i = 0; i < 8; ++i) {
        float s = 0.f, q = 0.f;
#pragma unroll
        for (int j = 0; j < 8; ++j) {
            float v = acc[i][j] + bb[j];
            acc[i][j] = v;
            s += v; q += v * v;
        }
#pragma unroll
        for (int o = 8; o > 0; o >>= 1) {
            s += __shfl_xor_sync(0xffffffffu, s, o);
            q += __shfl_xor_sync(0xffffffffu, q, o);
        }
        float mu  = s * (1.0f / 128.0f);
        float var = q * (1.0f / 128.0f) - mu * mu;
        float inv = rsqrtf(var + 1e-5f);
        int gm = m0 + ty * 8 + i;
        if (gm < NN) {
            float4 o0, o1;
            o0.x = fmaxf((acc[i][0] - mu) * inv * gg[0] + ee[0], 0.f);
            o0.y = fmaxf((acc[i][1] - mu) * inv * gg[1] + ee[1], 0.f);
            o0.z = fmaxf((acc[i][2] - mu) * inv * gg[2] + ee[2], 0.f);
            o0.w = fmaxf((acc[i][3] - mu) * inv * gg[3] + ee[3], 0.f);
            o1.x = fmaxf((acc[i][4] - mu) * inv * gg[4] + ee[4], 0.f);
            o1.y = fmaxf((acc[i][5] - mu) * inv * gg[5] + ee[5], 0.f);
            o1.z = fmaxf((acc[i][6] - mu) * inv * gg[6] + ee[6], 0.f);
            o1.w = fmaxf((acc[i][7] - mu) * inv * gg[7] + ee[7], 0.f);
            float* cp = C + (size_t)gm * ldc + noff + tx * 8;
            *(float4*)cp = o0;
            *(float4*)(cp + 4) = o1;
        }
    }
}

// ---------------- launch ----------------
extern "C" void kernel_launch(void* const* d_in, const int* in_sizes, int n_in,
                              void* d_out, int out_size)
{
    const void*  ei     = d_in[0];
    const float* feats  = (const float*)d_in[1];
    const float* W_uni  = (const float*)d_in[2];
    const float* b_uni  = (const float*)d_in[3];
    const float* g_uni  = (const float*)d_in[4];
    const float* be_uni = (const float*)d_in[5];
    const float* W_ind  = (const float*)d_in[6];
    const float* b_ind  = (const float*)d_in[7];
    const float* g_ind  = (const float*)d_in[8];
    const float* be_ind = (const float*)d_in[9];
    const float* W_rel  = (const float*)d_in[10];
    const float* b_rel  = (const float*)d_in[11];
    const float* g_rel  = (const float*)d_in[12];
    const float* be_rel = (const float*)d_in[13];
    float* out = (float*)d_out;

    float *ph, *pza, *pzb, *pcat, *pinv;
    cudaGetSymbolAddress((void**)&ph,   g_h);
    cudaGetSymbolAddress((void**)&pza,  g_za);
    cudaGetSymbolAddress((void**)&pzb,  g_zb);
    cudaGetSymbolAddress((void**)&pcat, g_cat);
    cudaGetSymbolAddress((void**)&pinv, g_invnorm);

    const int GEMM_GRID = (NN + 127) / 128;  // 782

    k_detect<<<1, 32>>>(ei);
    k_init_cnt<<<(NN + 255) / 256, 256>>>();
    k_invnorm<<<NN / 8, 256>>>(feats);
    k_count<<<(EE + 255) / 256, 256>>>(ei);
    k_scan1<<<NBLK, 1024>>>();
    k_scan2<<<1, 128>>>();
    k_scan3<<<NBLK, 1024>>>();
    k_scatter<<<(EE + 255) / 256, 256>>>();

    // h = MLP_uni(normalize(feats))
    k_gemm<KIN><<<GEMM_GRID, 256>>>(feats, KIN, pinv, W_uni, b_uni, g_uni, be_uni,
                                    ph, HF, 0);
    // hop 0 branch
    k_gemm<HF><<<GEMM_GRID, 256>>>(ph, HF, nullptr, W_ind, b_ind, g_ind, be_ind,
                                   pcat, 4 * HF, 0);
    // hop 1
    k_spmm<<<NN / 8, 256>>>(ph, pza);
    k_gemm<HF><<<GEMM_GRID, 256>>>(pza, HF, nullptr,
                                   W_ind + 1 * HF * HF, b_ind + 1 * HF,
                                   g_ind + 1 * HF, be_ind + 1 * HF,
                                   pcat, 4 * HF, 1 * HF);
    // hop 2
    k_spmm<<<NN / 8, 256>>>(pza, pzb);
    k_gemm<HF><<<GEMM_GRID, 256>>>(pzb, HF, nullptr,
                                   W_ind + 2 * HF * HF, b_ind + 2 * HF,
                                   g_ind + 2 * HF, be_ind + 2 * HF,
                                   pcat, 4 * HF, 2 * HF);
    // hop 3
    k_spmm<<<NN / 8, 256>>>(pzb, pza);
    k_gemm<HF><<<GEMM_GRID, 256>>>(pza, HF, nullptr,
                                   W_ind + 3 * HF * HF, b_ind + 3 * HF,
                                   g_ind + 3 * HF, be_ind + 3 * HF,
                                   pcat, 4 * HF, 3 * HF);
    // relation MLP on concat -> d_out
    k_gemm<4 * HF><<<GEMM_GRID, 256>>>(pcat, 4 * HF, nullptr, W_rel, b_rel, g_rel, be_rel,
                                       out, HF, 0);
}

// round 2
// speedup vs baseline: 1.0288x; 1.0288x over previous
#include <cuda_runtime.h>
#include <cstdint>
#include <cstddef>

#define NN 100000
#define EE 1600000
#define HF 128
#define KIN 512
#define NBLK 98   // ceil(NN/1024)

// ---------------- scratch (static device globals; no allocations) ----------------
__device__ int   g_is64;
__device__ float g_invnorm[NN];
__device__ int   g_cnt[NN];
__device__ float g_dinv[NN];
__device__ int   g_erow[EE];
__device__ int   g_ecol0[EE];
__device__ int   g_off[NN + 1];
__device__ int   g_cursor[NN];
__device__ int   g_bsum[128];
__device__ int   g_boff[128];
__device__ int   g_ecol[EE];
__device__ float g_ew[EE];
__device__ float g_h [(size_t)NN * HF];
__device__ float g_za[(size_t)NN * HF];
__device__ float g_zb[(size_t)NN * HF];
__device__ float g_cat[(size_t)NN * 4 * HF];

// ---------------- packed f32x2 helpers (FFMA2 — ptxas never emits this) ----------
__device__ __forceinline__ unsigned long long dup_f32x2(float x) {
    unsigned long long r;
    asm("mov.b64 %0, {%1, %1};" : "=l"(r) : "f"(x));
    return r;
}
__device__ __forceinline__ void fma_f32x2(unsigned long long& acc,
                                          unsigned long long a,
                                          unsigned long long b) {
    asm("fma.rn.f32x2 %0, %1, %2, %0;" : "+l"(acc) : "l"(a), "l"(b));
}
__device__ __forceinline__ void unpack_f32x2(unsigned long long v, float& lo, float& hi) {
    asm("mov.b64 {%0, %1}, %2;" : "=f"(lo), "=f"(hi) : "l"(v));
}

// ---------------- edge index width detection (int64 vs int32) ----------------
__global__ void k_detect(const void* ei) {
    const unsigned int* p = (const unsigned int*)ei;
    int ok64 = 1;
    for (int i = threadIdx.x; i < 64; i += 32)
        if (p[2 * i + 1] != 0u) ok64 = 0;
    ok64 = __all_sync(0xffffffffu, ok64);
    if (threadIdx.x == 0) g_is64 = ok64;
}

__global__ void k_init_cnt() {
    int i = blockIdx.x * blockDim.x + threadIdx.x;
    if (i < NN) g_cnt[i] = 0;
}

// row-norm of features: invnorm[i] = 1 / max(||feats[i]||, 1e-12)
__global__ void k_invnorm(const float* __restrict__ feats) {
    int w = (blockIdx.x * blockDim.x + threadIdx.x) >> 5;
    int lane = threadIdx.x & 31;
    if (w >= NN) return;
    const float4* p = (const float4*)(feats + (size_t)w * KIN);
    float ss = 0.f;
#pragma unroll
    for (int i = 0; i < 4; ++i) {
        float4 v = p[i * 32 + lane];
        ss += v.x * v.x + v.y * v.y + v.z * v.z + v.w * v.w;
    }
#pragma unroll
    for (int o = 16; o > 0; o >>= 1) ss += __shfl_xor_sync(0xffffffffu, ss, o);
    if (lane == 0) g_invnorm[w] = 1.0f / fmaxf(sqrtf(ss), 1e-12f);
}

// convert edges to int32 + count out-degree (rows)
__global__ void k_count(const void* ei) {
    int e = blockIdx.x * blockDim.x + threadIdx.x;
    if (e >= EE) return;
    int r, c;
    if (g_is64) {
        const long long* p = (const long long*)ei;
        r = (int)p[e]; c = (int)p[EE + e];
    } else {
        const int* p = (const int*)ei;
        r = p[e]; c = p[EE + e];
    }
    g_erow[e] = r;
    g_ecol0[e] = c;
    atomicAdd(&g_cnt[r], 1);
}

// exclusive scan of g_cnt -> g_off (3 kernels, block size 1024)
__global__ void k_scan1() {
    __shared__ int sm[1024];
    int t = threadIdx.x;
    int i = blockIdx.x * 1024 + t;
    int v = (i < NN) ? g_cnt[i] : 0;
    sm[t] = v;
    __syncthreads();
    for (int d = 1; d < 1024; d <<= 1) {
        int add = (t >= d) ? sm[t - d] : 0;
        __syncthreads();
        sm[t] += add;
        __syncthreads();
    }
    int incl = sm[t];
    if (i < NN) g_off[i] = incl - v;
    if (t == 1023) g_bsum[blockIdx.x] = incl;
}

__global__ void k_scan2() {
    __shared__ int sm[128];
    int t = threadIdx.x;
    int v = (t < NBLK) ? g_bsum[t] : 0;
    sm[t] = v;
    __syncthreads();
    for (int d = 1; d < 128; d <<= 1) {
        int add = (t >= d) ? sm[t - d] : 0;
        __syncthreads();
        sm[t] += add;
        __syncthreads();
    }
    g_boff[t] = sm[t] - v;
}

__global__ void k_scan3() {
    int t = threadIdx.x;
    int i = blockIdx.x * 1024 + t;
    if (i < NN) {
        int off = g_off[i] + g_boff[blockIdx.x];
        g_off[i] = off;
        g_cursor[i] = off;
        g_dinv[i] = rsqrtf((float)(g_cnt[i] + 1));   // +1 for self loop
        if (i == 0) g_off[NN] = EE;
    }
}

__global__ void k_scatter() {
    int e = blockIdx.x * blockDim.x + threadIdx.x;
    if (e >= EE) return;
    int r = g_erow[e], c = g_ecol0[e];
    int pos = atomicAdd(&g_cursor[r], 1);
    g_ecol[pos] = c;
    g_ew[pos] = g_dinv[r] * g_dinv[c];
}

// warp-per-node SpMM with self-loop, CSR, register accumulation (no atomics)
__global__ void k_spmm(const float* __restrict__ zin, float* __restrict__ zout) {
    int w = (blockIdx.x * blockDim.x + threadIdx.x) >> 5;
    int lane = threadIdx.x & 31;
    if (w >= NN) return;
    int s = g_off[w], e = g_off[w + 1];
    float dn = g_dinv[w];
    float ws = dn * dn;
    float4 acc = ((const float4*)(zin + (size_t)w * HF))[lane];
    acc.x *= ws; acc.y *= ws; acc.z *= ws; acc.w *= ws;
#pragma unroll 4
    for (int j = s; j < e; ++j) {
        int c = g_ecol[j];
        float wt = g_ew[j];
        float4 v = ((const float4*)(zin + (size_t)c * HF))[lane];
        acc.x += wt * v.x; acc.y += wt * v.y; acc.z += wt * v.z; acc.w += wt * v.w;
    }
    ((float4*)(zout + (size_t)w * HF))[lane] = acc;
}

// ---------------- fused GEMM + bias + LayerNorm + ReLU ----------------
// C[m, noff + n] = relu(LN(A[m,:K] (*rowscale[m]) @ B[K,128] + bias) * gamma + beta)
// Inner product uses packed fma.rn.f32x2 (FFMA2) -> 2 fp32 FMA per fma-pipe slot.
template <int K>
__global__ __launch_bounds__(256, 2)
void k_gemm(const float* __restrict__ A, int lda, const float* __restrict__ rowscale,
            const float* __restrict__ B,
            const float* __restrict__ bias, const float* __restrict__ gamma,
            const float* __restrict__ beta,
            float* __restrict__ C, int ldc, int noff)
{
    __shared__ float As[16][128];
    __shared__ float Bs[16][128];
    int m0 = blockIdx.x * 128;
    int t = threadIdx.x;
    int tx = t & 15, ty = t >> 4;

    unsigned long long acc2[8][4];
#pragma unroll
    for (int i = 0; i < 8; ++i)
#pragma unroll
        for (int j = 0; j < 4; ++j) acc2[i][j] = 0ULL;

    for (int k0 = 0; k0 < K; k0 += 16) {
        // A tile -> smem (k-major), with optional per-row scale
#pragma unroll
        for (int it = 0; it < 2; ++it) {
            int f = t + it * 256;
            int row = f >> 2, kq = (f & 3) * 4;
            int gm = m0 + row;
            float4 av = make_float4(0.f, 0.f, 0.f, 0.f);
            if (gm < NN) {
                av = *(const float4*)(A + (size_t)gm * lda + k0 + kq);
                if (rowscale) {
                    float sc = rowscale[gm];
                    av.x *= sc; av.y *= sc; av.z *= sc; av.w *= sc;
                }
            }
            As[kq + 0][row] = av.x;
            As[kq + 1][row] = av.y;
            As[kq + 2][row] = av.z;
            As[kq + 3][row] = av.w;
        }
        // B tile -> smem
#pragma unroll
        for (int it = 0; it < 2; ++it) {
            int f = t + it * 256;
            int kk = f >> 5, n4 = (f & 31) * 4;
            *(float4*)&Bs[kk][n4] = *(const float4*)(B + (size_t)(k0 + kk) * HF + n4);
        }
        __syncthreads();
#pragma unroll
        for (int kk = 0; kk < 16; ++kk) {
            float a[8];
            unsigned long long b2[4];
            *(float4*)&a[0] = *(const float4*)&As[kk][ty * 8];
            *(float4*)&a[4] = *(const float4*)&As[kk][ty * 8 + 4];
            // B pairs are contiguous in smem: read directly as 64-bit packs
            {
                const ulonglong2* bp = (const ulonglong2*)&Bs[kk][tx * 8];
                ulonglong2 p0 = bp[0];
                ulonglong2 p1 = bp[1];
                b2[0] = p0.x; b2[1] = p0.y; b2[2] = p1.x; b2[3] = p1.y;
            }
#pragma unroll
            for (int i = 0; i < 8; ++i) {
                unsigned long long a2 = dup_f32x2(a[i]);
#pragma unroll
                for (int j = 0; j < 4; ++j) fma_f32x2(acc2[i][j], a2, b2[j]);
            }
        }
        __syncthreads();
    }

    // epilogue: bias, LN over the 128-wide row (16 tx threads per row), relu
    float bb[8], gg[8], ee[8];
#pragma unroll
    for (int j = 0; j < 8; ++j) {
        int c = tx * 8 + j;
        bb[j] = bias[c]; gg[j] = gamma[c]; ee[j] = beta[c];
    }
#pragma unroll
    for (int i = 0; i < 8; ++i) {
        float v[8];
#pragma unroll
        for (int j = 0; j < 4; ++j) unpack_f32x2(acc2[i][j], v[2 * j], v[2 * j + 1]);
        float s = 0.f, q = 0.f;
#pragma unroll
        for (int j = 0; j < 8; ++j) {
            float x = v[j] + bb[j];
            v[j] = x;
            s += x; q += x * x;
        }
#pragma unroll
        for (int o = 8; o > 0; o >>= 1) {
            s += __shfl_xor_sync(0xffffffffu, s, o);
            q += __shfl_xor_sync(0xffffffffu, q, o);
        }
        float mu  = s * (1.0f / 128.0f);
        float var = q * (1.0f / 128.0f) - mu * mu;
        float inv = rsqrtf(var + 1e-5f);
        int gm = m0 + ty * 8 + i;
        if (gm < NN) {
            float4 o0, o1;
            o0.x = fmaxf((v[0] - mu) * inv * gg[0] + ee[0], 0.f);
            o0.y = fmaxf((v[1] - mu) * inv * gg[1] + ee[1], 0.f);
            o0.z = fmaxf((v[2] - mu) * inv * gg[2] + ee[2], 0.f);
            o0.w = fmaxf((v[3] - mu) * inv * gg[3] + ee[3], 0.f);
            o1.x = fmaxf((v[4] - mu) * inv * gg[4] + ee[4], 0.f);
            o1.y = fmaxf((v[5] - mu) * inv * gg[5] + ee[5], 0.f);
            o1.z = fmaxf((v[6] - mu) * inv * gg[6] + ee[6], 0.f);
            o1.w = fmaxf((v[7] - mu) * inv * gg[7] + ee[7], 0.f);
            float* cp = C + (size_t)gm * ldc + noff + tx * 8;
            *(float4*)cp = o0;
            *(float4*)(cp + 4) = o1;
        }
    }
}

// ---------------- launch ----------------
extern "C" void kernel_launch(void* const* d_in, const int* in_sizes, int n_in,
                              void* d_out, int out_size)
{
    const void*  ei     = d_in[0];
    const float* feats  = (const float*)d_in[1];
    const float* W_uni  = (const float*)d_in[2];
    const float* b_uni  = (const float*)d_in[3];
    const float* g_uni  = (const float*)d_in[4];
    const float* be_uni = (const float*)d_in[5];
    const float* W_ind  = (const float*)d_in[6];
    const float* b_ind  = (const float*)d_in[7];
    const float* g_ind  = (const float*)d_in[8];
    const float* be_ind = (const float*)d_in[9];
    const float* W_rel  = (const float*)d_in[10];
    const float* b_rel  = (const float*)d_in[11];
    const float* g_rel  = (const float*)d_in[12];
    const float* be_rel = (const float*)d_in[13];
    float* out = (float*)d_out;

    float *ph, *pza, *pzb, *pcat, *pinv;
    cudaGetSymbolAddress((void**)&ph,   g_h);
    cudaGetSymbolAddress((void**)&pza,  g_za);
    cudaGetSymbolAddress((void**)&pzb,  g_zb);
    cudaGetSymbolAddress((void**)&pcat, g_cat);
    cudaGetSymbolAddress((void**)&pinv, g_invnorm);

    const int GEMM_GRID = (NN + 127) / 128;  // 782

    k_detect<<<1, 32>>>(ei);
    k_init_cnt<<<(NN + 255) / 256, 256>>>();
    k_invnorm<<<NN / 8, 256>>>(feats);
    k_count<<<(EE + 255) / 256, 256>>>(ei);
    k_scan1<<<NBLK, 1024>>>();
    k_scan2<<<1, 128>>>();
    k_scan3<<<NBLK, 1024>>>();
    k_scatter<<<(EE + 255) / 256, 256>>>();

    // h = MLP_uni(normalize(feats))
    k_gemm<KIN><<<GEMM_GRID, 256>>>(feats, KIN, pinv, W_uni, b_uni, g_uni, be_uni,
                                    ph, HF, 0);
    // hop 0 branch
    k_gemm<HF><<<GEMM_GRID, 256>>>(ph, HF, nullptr, W_ind, b_ind, g_ind, be_ind,
                                   pcat, 4 * HF, 0);
    // hop 1
    k_spmm<<<NN / 8, 256>>>(ph, pza);
    k_gemm<HF><<<GEMM_GRID, 256>>>(pza, HF, nullptr,
                                   W_ind + 1 * HF * HF, b_ind + 1 * HF,
                                   g_ind + 1 * HF, be_ind + 1 * HF,
                                   pcat, 4 * HF, 1 * HF);
    // hop 2
    k_spmm<<<NN / 8, 256>>>(pza, pzb);
    k_gemm<HF><<<GEMM_GRID, 256>>>(pzb, HF, nullptr,
                                   W_ind + 2 * HF * HF, b_ind + 2 * HF,
                                   g_ind + 2 * HF, be_ind + 2 * HF,
                                   pcat, 4 * HF, 2 * HF);
    // hop 3
    k_spmm<<<NN / 8, 256>>>(pzb, pza);
    k_gemm<HF><<<GEMM_GRID, 256>>>(pza, HF, nullptr,
                                   W_ind + 3 * HF * HF, b_ind + 3 * HF,
                                   g_ind + 3 * HF, be_ind + 3 * HF,
                                   pcat, 4 * HF, 3 * HF);
    // relation MLP on concat -> d_out
    k_gemm<4 * HF><<<GEMM_GRID, 256>>>(pcat, 4 * HF, nullptr, W_rel, b_rel, g_rel, be_rel,
                                       out, HF, 0);
}

// round 4
// speedup vs baseline: 1.2461x; 1.2113x over previous
#include <cuda_runtime.h>
#include <cuda_bf16.h>
#include <cstdint>
#include <cstddef>

#define NN 100000
#define EE 1600000
#define HF 128
#define KIN 512
#define NBLK 98     // ceil(NN/1024)
#define GRID_M 782  // ceil(NN/128)
#define BK 32
#define ASTR 40     // padded smem row stride (bf16 elems): 80B rows -> conflict-free LDSM

typedef __nv_bfloat16 bf16;

// ---------------- scratch (static device globals; no allocations) ----------------
__device__ int   g_is64;
__device__ float g_invnorm[NN];
__device__ int   g_cnt[NN];
__device__ float g_dinv[NN];
__device__ int   g_erow[EE];
__device__ int   g_ecol0[EE];
__device__ int   g_off[NN + 1];
__device__ int   g_cursor[NN];
__device__ int   g_bsum[128];
__device__ int   g_boff[128];
__device__ int   g_ecol[EE];
__device__ float g_ew[EE];

__device__ float g_h  [(size_t)NN * HF];
__device__ float g_za [(size_t)NN * HF];
__device__ float g_zb [(size_t)NN * HF];
__device__ float g_cat[(size_t)NN * 4 * HF];

// transposed + hi/lo split weights: Wt[n][k] = W[k][n]
__device__ bf16 g_wu_hi[HF * KIN];
__device__ bf16 g_wu_lo[HF * KIN];
__device__ bf16 g_wi_hi[4 * HF * HF];
__device__ bf16 g_wi_lo[4 * HF * HF];
__device__ bf16 g_wr_hi[HF * KIN];
__device__ bf16 g_wr_lo[HF * KIN];

// ---------------- helpers ----------------
__device__ __forceinline__ uint32_t smem_to_u32(const void* p) {
    uint32_t a;
    asm("{ .reg .u64 t; cvta.to.shared.u64 t, %1; cvt.u32.u64 %0, t; }" : "=r"(a) : "l"(p));
    return a;
}
__device__ __forceinline__ uint32_t bpack(bf16 a, bf16 b) {
    __nv_bfloat162 t(a, b);
    return *reinterpret_cast<uint32_t*>(&t);
}
__device__ __forceinline__ void split2(float a, float b, uint32_t& hi, uint32_t& lo) {
    bf16 ha = __float2bfloat16(a), hb = __float2bfloat16(b);
    float ra = a - __bfloat162float(ha);
    float rb = b - __bfloat162float(hb);
    hi = bpack(ha, hb);
    lo = bpack(__float2bfloat16(ra), __float2bfloat16(rb));
}
__device__ __forceinline__ void ldsm4(uint32_t* r, uint32_t a) {
    asm volatile("ldmatrix.sync.aligned.m8n8.x4.shared.b16 {%0,%1,%2,%3}, [%4];"
        : "=r"(r[0]), "=r"(r[1]), "=r"(r[2]), "=r"(r[3]) : "r"(a));
}
__device__ __forceinline__ void ldsm2(uint32_t* r, uint32_t a) {
    asm volatile("ldmatrix.sync.aligned.m8n8.x2.shared.b16 {%0,%1}, [%2];"
        : "=r"(r[0]), "=r"(r[1]) : "r"(a));
}
__device__ __forceinline__ void mma16816(float* c, const uint32_t* a, const uint32_t* b) {
    asm volatile("mma.sync.aligned.m16n8k16.row.col.f32.bf16.bf16.f32 "
        "{%0,%1,%2,%3}, {%4,%5,%6,%7}, {%8,%9}, {%0,%1,%2,%3};"
        : "+f"(c[0]), "+f"(c[1]), "+f"(c[2]), "+f"(c[3])
        : "r"(a[0]), "r"(a[1]), "r"(a[2]), "r"(a[3]), "r"(b[0]), "r"(b[1]));
}

// ---------------- preprocessing ----------------
__global__ void k_detect(const void* ei) {
    const unsigned int* p = (const unsigned int*)ei;
    int ok64 = 1;
    for (int i = threadIdx.x; i < 64; i += 32)
        if (p[2 * i + 1] != 0u) ok64 = 0;
    ok64 = __all_sync(0xffffffffu, ok64);
    if (threadIdx.x == 0) g_is64 = ok64;
}

__global__ void k_init_cnt() {
    int i = blockIdx.x * blockDim.x + threadIdx.x;
    if (i < NN) g_cnt[i] = 0;
}

__global__ void k_invnorm(const float* __restrict__ feats) {
    int w = (blockIdx.x * blockDim.x + threadIdx.x) >> 5;
    int lane = threadIdx.x & 31;
    if (w >= NN) return;
    const float4* p = (const float4*)(feats + (size_t)w * KIN);
    float ss = 0.f;
#pragma unroll
    for (int i = 0; i < 4; ++i) {
        float4 v = p[i * 32 + lane];
        ss += v.x * v.x + v.y * v.y + v.z * v.z + v.w * v.w;
    }
#pragma unroll
    for (int o = 16; o > 0; o >>= 1) ss += __shfl_xor_sync(0xffffffffu, ss, o);
    if (lane == 0) g_invnorm[w] = 1.0f / fmaxf(sqrtf(ss), 1e-12f);
}

__global__ void k_count(const void* ei) {
    int e = blockIdx.x * blockDim.x + threadIdx.x;
    if (e >= EE) return;
    int r, c;
    if (g_is64) {
        const long long* p = (const long long*)ei;
        r = (int)p[e]; c = (int)p[EE + e];
    } else {
        const int* p = (const int*)ei;
        r = p[e]; c = p[EE + e];
    }
    g_erow[e] = r;
    g_ecol0[e] = c;
    atomicAdd(&g_cnt[r], 1);
}

__global__ void k_scan1() {
    __shared__ int sm[1024];
    int t = threadIdx.x;
    int i = blockIdx.x * 1024 + t;
    int v = (i < NN) ? g_cnt[i] : 0;
    sm[t] = v;
    __syncthreads();
    for (int d = 1; d < 1024; d <<= 1) {
        int add = (t >= d) ? sm[t - d] : 0;
        __syncthreads();
        sm[t] += add;
        __syncthreads();
    }
    int incl = sm[t];
    if (i < NN) g_off[i] = incl - v;
    if (t == 1023) g_bsum[blockIdx.x] = incl;
}

__global__ void k_scan2() {
    __shared__ int sm[128];
    int t = threadIdx.x;
    int v = (t < NBLK) ? g_bsum[t] : 0;
    sm[t] = v;
    __syncthreads();
    for (int d = 1; d < 128; d <<= 1) {
        int add = (t >= d) ? sm[t - d] : 0;
        __syncthreads();
        sm[t] += add;
        __syncthreads();
    }
    g_boff[t] = sm[t] - v;
}

__global__ void k_scan3() {
    int t = threadIdx.x;
    int i = blockIdx.x * 1024 + t;
    if (i < NN) {
        int off = g_off[i] + g_boff[blockIdx.x];
        g_off[i] = off;
        g_cursor[i] = off;
        g_dinv[i] = rsqrtf((float)(g_cnt[i] + 1));
        if (i == 0) g_off[NN] = EE;
    }
}

__global__ void k_scatter() {
    int e = blockIdx.x * blockDim.x + threadIdx.x;
    if (e >= EE) return;
    int r = g_erow[e], c = g_ecol0[e];
    int pos = atomicAdd(&g_cursor[r], 1);
    g_ecol[pos] = c;
    g_ew[pos] = g_dinv[r] * g_dinv[c];
}

// weight transpose + split: out[m][n][k] = W[m][k][n]
__global__ void k_wprep(const float* __restrict__ W, bf16* __restrict__ hi,
                        bf16* __restrict__ lo, int K, int total) {
    int o = blockIdx.x * blockDim.x + threadIdx.x;
    if (o >= total) return;
    int k = o % K;
    int rem = o / K;
    int n = rem % HF;
    int m = rem / HF;
    float x = W[(size_t)m * K * HF + (size_t)k * HF + n];
    bf16 h = __float2bfloat16(x);
    hi[o] = h;
    lo[o] = __float2bfloat16(x - __bfloat162float(h));
}

// warp-per-node SpMM with self-loop, CSR, register accumulation (no atomics)
__global__ void k_spmm(const float* __restrict__ zin, float* __restrict__ zout) {
    int w = (blockIdx.x * blockDim.x + threadIdx.x) >> 5;
    int lane = threadIdx.x & 31;
    if (w >= NN) return;
    int s = g_off[w], e = g_off[w + 1];
    float dn = g_dinv[w];
    float ws = dn * dn;
    float4 acc = ((const float4*)(zin + (size_t)w * HF))[lane];
    acc.x *= ws; acc.y *= ws; acc.z *= ws; acc.w *= ws;
#pragma unroll 4
    for (int j = s; j < e; ++j) {
        int c = g_ecol[j];
        float wt = g_ew[j];
        float4 v = ((const float4*)(zin + (size_t)c * HF))[lane];
        acc.x += wt * v.x; acc.y += wt * v.y; acc.z += wt * v.z; acc.w += wt * v.w;
    }
    ((float4*)(zout + (size_t)w * HF))[lane] = acc;
}

// ---------------- HMMA bf16 3-term GEMM + bias + LayerNorm + ReLU ----------------
// C[m, noff+n] = relu(LN(A[m,:K](*rowscale) @ Wt[n,:K] + bias) * gamma + beta)
#define OFF_AH 0
#define OFF_AL (128 * ASTR * 2)
#define OFF_BH (2 * 128 * ASTR * 2)
#define OFF_BL (3 * 128 * ASTR * 2)
#define SMEM_DYN (128 * 129 * 4)   // 66048 (stg reuse dominates operand tiles 40960)

template <int K>
__global__ __launch_bounds__(256, 1)
void k_mma(const float* __restrict__ A, int lda, const float* __restrict__ rowscale,
           const bf16* __restrict__ Whi, const bf16* __restrict__ Wlo,
           const float* __restrict__ bias, const float* __restrict__ gamma,
           const float* __restrict__ beta,
           float* __restrict__ C, int ldc, int noff)
{
    extern __shared__ char smem[];
    bf16* sAh = (bf16*)(smem + OFF_AH);
    bf16* sAl = (bf16*)(smem + OFF_AL);
    bf16* sBh = (bf16*)(smem + OFF_BH);
    bf16* sBl = (bf16*)(smem + OFF_BL);
    float* stg = (float*)smem;   // [128][129], reused after mainloop
    uint32_t sbase = smem_to_u32(smem);

    const int t = threadIdx.x, lane = t & 31, wid = t >> 5;
    const int warp_m = wid & 1, warp_n = wid >> 1;   // 2 (M) x 4 (N)
    const int m0 = blockIdx.x * 128;

    float acc[4][4][4];
#pragma unroll
    for (int i = 0; i < 4; ++i)
#pragma unroll
        for (int j = 0; j < 4; ++j)
#pragma unroll
            for (int u = 0; u < 4; ++u) acc[i][j][u] = 0.f;

    // precomputed ldmatrix lane addressing
    const int a_row = warp_m * 64 + (lane & 7) + ((lane >> 3) & 1) * 8;
    const int a_col = (lane >> 4) * 8;
    const int b_row = warp_n * 32 + (lane & 7);
    const int b_col = ((lane >> 3) & 1) * 8;

    for (int k0 = 0; k0 < K; k0 += BK) {
        // ---- stage A (fp32 -> hi/lo bf16) and B (pre-split bf16) ----
        for (int i = t; i < 1024; i += 256) {
            int row = i >> 3, cq = (i & 7) * 4;
            float4 v = make_float4(0.f, 0.f, 0.f, 0.f);
            int gm = m0 + row;
            if (gm < NN) {
                v = *(const float4*)(A + (size_t)gm * lda + k0 + cq);
                if (rowscale) {
                    float sc = rowscale[gm];
                    v.x *= sc; v.y *= sc; v.z *= sc; v.w *= sc;
                }
            }
            uint2 H, L;
            split2(v.x, v.y, H.x, L.x);
            split2(v.z, v.w, H.y, L.y);
            *(uint2*)(sAh + row * ASTR + cq) = H;
            *(uint2*)(sAl + row * ASTR + cq) = L;
            *(uint2*)(sBh + row * ASTR + cq) = *(const uint2*)(Whi + (size_t)row * K + k0 + cq);
            *(uint2*)(sBl + row * ASTR + cq) = *(const uint2*)(Wlo + (size_t)row * K + k0 + cq);
        }
        __syncthreads();

#pragma unroll
        for (int kk = 0; kk < BK; kk += 16) {
            uint32_t bh[4][2], bl[4][2];
#pragma unroll
            for (int nt = 0; nt < 4; ++nt) {
                uint32_t boff = (uint32_t)(((b_row + nt * 8) * ASTR + kk + b_col) * 2);
                ldsm2(bh[nt], sbase + OFF_BH + boff);
                ldsm2(bl[nt], sbase + OFF_BL + boff);
            }
#pragma unroll
            for (int mt = 0; mt < 4; ++mt) {
                uint32_t ah[4], al[4];
                uint32_t aoff = (uint32_t)(((a_row + mt * 16) * ASTR + kk + a_col) * 2);
                ldsm4(ah, sbase + OFF_AH + aoff);
                ldsm4(al, sbase + OFF_AL + aoff);
#pragma unroll
                for (int nt = 0; nt < 4; ++nt) {
                    mma16816(acc[mt][nt], ah, bh[nt]);
                    mma16816(acc[mt][nt], ah, bl[nt]);
                    mma16816(acc[mt][nt], al, bh[nt]);
                }
            }
        }
        __syncthreads();
    }

    // ---- stage accumulators to smem (stride 129: conflict-free column reads) ----
#pragma unroll
    for (int mt = 0; mt < 4; ++mt) {
#pragma unroll
        for (int nt = 0; nt < 4; ++nt) {
            int r0 = warp_m * 64 + mt * 16 + (lane >> 2);
            int cc = warp_n * 32 + nt * 8 + (lane & 3) * 2;
            stg[r0 * 129 + cc]         = acc[mt][nt][0];
            stg[r0 * 129 + cc + 1]     = acc[mt][nt][1];
            stg[(r0 + 8) * 129 + cc]     = acc[mt][nt][2];
            stg[(r0 + 8) * 129 + cc + 1] = acc[mt][nt][3];
        }
    }
    __syncthreads();

    // ---- warp-per-row bias + LN + ReLU, coalesced fp32 writes ----
    for (int r = wid; r < 128; r += 8) {
        int gm = m0 + r;
        int c = lane * 4;
        float x0 = stg[r * 129 + c]     + bias[c];
        float x1 = stg[r * 129 + c + 1] + bias[c + 1];
        float x2 = stg[r * 129 + c + 2] + bias[c + 2];
        float x3 = stg[r * 129 + c + 3] + bias[c + 3];
        float s = x0 + x1 + x2 + x3;
        float q = x0 * x0 + x1 * x1 + x2 * x2 + x3 * x3;
#pragma unroll
        for (int o = 16; o > 0; o >>= 1) {
            s += __shfl_xor_sync(0xffffffffu, s, o);
            q += __shfl_xor_sync(0xffffffffu, q, o);
        }
        float mu  = s * (1.0f / 128.0f);
        float var = q * (1.0f / 128.0f) - mu * mu;
        float inv = rsqrtf(var + 1e-5f);
        if (gm < NN) {
            float4 y;
            y.x = fmaxf((x0 - mu) * inv * gamma[c]     + beta[c],     0.f);
            y.y = fmaxf((x1 - mu) * inv * gamma[c + 1] + beta[c + 1], 0.f);
            y.z = fmaxf((x2 - mu) * inv * gamma[c + 2] + beta[c + 2], 0.f);
            y.w = fmaxf((x3 - mu) * inv * gamma[c + 3] + beta[c + 3], 0.f);
            *(float4*)(C + (size_t)gm * ldc + noff + c) = y;
        }
    }
}

// ---------------- launch ----------------
extern "C" void kernel_launch(void* const* d_in, const int* in_sizes, int n_in,
                              void* d_out, int out_size)
{
    const void*  ei     = d_in[0];
    const float* feats  = (const float*)d_in[1];
    const float* W_uni  = (const float*)d_in[2];
    const float* b_uni  = (const float*)d_in[3];
    const float* g_uni  = (const float*)d_in[4];
    const float* be_uni = (const float*)d_in[5];
    const float* W_ind  = (const float*)d_in[6];
    const float* b_ind  = (const float*)d_in[7];
    const float* g_ind  = (const float*)d_in[8];
    const float* be_ind = (const float*)d_in[9];
    const float* W_rel  = (const float*)d_in[10];
    const float* b_rel  = (const float*)d_in[11];
    const float* g_rel  = (const float*)d_in[12];
    const float* be_rel = (const float*)d_in[13];
    float* out = (float*)d_out;

    cudaFuncSetAttribute(k_mma<KIN>, cudaFuncAttributeMaxDynamicSharedMemorySize, SMEM_DYN);
    cudaFuncSetAttribute(k_mma<HF>,  cudaFuncAttributeMaxDynamicSharedMemorySize, SMEM_DYN);

    float *ph, *pza, *pzb, *pcat, *pinv;
    bf16 *pwuh, *pwul, *pwih, *pwil, *pwrh, *pwrl;
    cudaGetSymbolAddress((void**)&ph,   g_h);
    cudaGetSymbolAddress((void**)&pza,  g_za);
    cudaGetSymbolAddress((void**)&pzb,  g_zb);
    cudaGetSymbolAddress((void**)&pcat, g_cat);
    cudaGetSymbolAddress((void**)&pinv, g_invnorm);
    cudaGetSymbolAddress((void**)&pwuh, g_wu_hi);
    cudaGetSymbolAddress((void**)&pwul, g_wu_lo);
    cudaGetSymbolAddress((void**)&pwih, g_wi_hi);
    cudaGetSymbolAddress((void**)&pwil, g_wi_lo);
    cudaGetSymbolAddress((void**)&pwrh, g_wr_hi);
    cudaGetSymbolAddress((void**)&pwrl, g_wr_lo);

    // ---- graph preprocessing ----
    k_detect<<<1, 32>>>(ei);
    k_init_cnt<<<(NN + 255) / 256, 256>>>();
    k_invnorm<<<NN / 8, 256>>>(feats);
    k_count<<<(EE + 255) / 256, 256>>>(ei);
    k_scan1<<<NBLK, 1024>>>();
    k_scan2<<<1, 128>>>();
    k_scan3<<<NBLK, 1024>>>();
    k_scatter<<<(EE + 255) / 256, 256>>>();

    // ---- weight prep (transpose + bf16 hi/lo split) ----
    k_wprep<<<(HF * KIN + 255) / 256, 256>>>(W_uni, pwuh, pwul, KIN, HF * KIN);
    k_wprep<<<(4 * HF * HF + 255) / 256, 256>>>(W_ind, pwih, pwil, HF, 4 * HF * HF);
    k_wprep<<<(HF * KIN + 255) / 256, 256>>>(W_rel, pwrh, pwrl, KIN, HF * KIN);

    // ---- h = MLP_uni(normalize(feats)) ----
    k_mma<KIN><<<GRID_M, 256, SMEM_DYN>>>(feats, KIN, pinv, pwuh, pwul,
                                          b_uni, g_uni, be_uni, ph, HF, 0);
    // hop 0
    k_mma<HF><<<GRID_M, 256, SMEM_DYN>>>(ph, HF, nullptr, pwih, pwil,
                                         b_ind, g_ind, be_ind, pcat, 4 * HF, 0);
    // hop 1
    k_spmm<<<NN / 8, 256>>>(ph, pza);
    k_mma<HF><<<GRID_M, 256, SMEM_DYN>>>(pza, HF, nullptr,
                                         pwih + 1 * HF * HF, pwil + 1 * HF * HF,
                                         b_ind + 1 * HF, g_ind + 1 * HF, be_ind + 1 * HF,
                                         pcat, 4 * HF, 1 * HF);
    // hop 2
    k_spmm<<<NN / 8, 256>>>(pza, pzb);
    k_mma<HF><<<GRID_M, 256, SMEM_DYN>>>(pzb, HF, nullptr,
                                         pwih + 2 * HF * HF, pwil + 2 * HF * HF,
                                         b_ind + 2 * HF, g_ind + 2 * HF, be_ind + 2 * HF,
                                         pcat, 4 * HF, 2 * HF);
    // hop 3
    k_spmm<<<NN / 8, 256>>>(pzb, pza);
    k_mma<HF><<<GRID_M, 256, SMEM_DYN>>>(pza, HF, nullptr,
                                         pwih + 3 * HF * HF, pwil + 3 * HF * HF,
                                         b_ind + 3 * HF, g_ind + 3 * HF, be_ind + 3 * HF,
                                         pcat, 4 * HF, 3 * HF);
    // relation MLP -> d_out
    k_mma<KIN><<<GRID_M, 256, SMEM_DYN>>>(pcat, 4 * HF, nullptr, pwrh, pwrl,
                                          b_rel, g_rel, be_rel, out, HF, 0);
}

// round 5
// speedup vs baseline: 1.7368x; 1.3938x over previous
#include <cuda_runtime.h>
#include <cuda_bf16.h>
#include <cstdint>
#include <cstddef>

#define NN 100000
#define EE 1600000
#define HF 128
#define KIN 512
#define NBLK 98     // ceil(NN/1024)
#define GRID_M 782  // ceil(NN/128)
#define BK 64
#define ASTR 72     // padded smem row stride (bf16 elems): 144B rows -> conflict-free LDSM

typedef __nv_bfloat16 bf16;

// ---------------- scratch (static device globals; no allocations) ----------------
__device__ int   g_is64;
__device__ float g_invnorm[NN];
__device__ int   g_cnt[NN];
__device__ float g_dinv[NN];
__device__ int   g_erow[EE];
__device__ int   g_ecol0[EE];
__device__ int   g_off[NN + 1];
__device__ int   g_cursor[NN];
__device__ int   g_bsum[128];
__device__ int   g_boff[128];
__device__ int   g_ecol[EE];
__device__ float g_ew[EE];

__device__ float g_h  [(size_t)NN * HF];
__device__ float g_za [(size_t)NN * HF];
__device__ float g_zb [(size_t)NN * HF];
__device__ float g_cat[(size_t)NN * 4 * HF];

// transposed + hi/lo split weights: Wt[n][k] = W[k][n]
__device__ bf16 g_wu_hi[HF * KIN];
__device__ bf16 g_wu_lo[HF * KIN];
__device__ bf16 g_wi_hi[4 * HF * HF];
__device__ bf16 g_wi_lo[4 * HF * HF];
__device__ bf16 g_wr_hi[HF * KIN];
__device__ bf16 g_wr_lo[HF * KIN];

// ---------------- helpers ----------------
__device__ __forceinline__ uint32_t smem_to_u32(const void* p) {
    uint32_t a;
    asm("{ .reg .u64 t; cvta.to.shared.u64 t, %1; cvt.u32.u64 %0, t; }" : "=r"(a) : "l"(p));
    return a;
}
__device__ __forceinline__ uint32_t bpack(bf16 a, bf16 b) {
    __nv_bfloat162 t(a, b);
    return *reinterpret_cast<uint32_t*>(&t);
}
__device__ __forceinline__ void split2(float a, float b, uint32_t& hi, uint32_t& lo) {
    bf16 ha = __float2bfloat16(a), hb = __float2bfloat16(b);
    float ra = a - __bfloat162float(ha);
    float rb = b - __bfloat162float(hb);
    hi = bpack(ha, hb);
    lo = bpack(__float2bfloat16(ra), __float2bfloat16(rb));
}
__device__ __forceinline__ void ldsm4(uint32_t* r, uint32_t a) {
    asm volatile("ldmatrix.sync.aligned.m8n8.x4.shared.b16 {%0,%1,%2,%3}, [%4];"
        : "=r"(r[0]), "=r"(r[1]), "=r"(r[2]), "=r"(r[3]) : "r"(a));
}
__device__ __forceinline__ void ldsm2(uint32_t* r, uint32_t a) {
    asm volatile("ldmatrix.sync.aligned.m8n8.x2.shared.b16 {%0,%1}, [%2];"
        : "=r"(r[0]), "=r"(r[1]) : "r"(a));
}
__device__ __forceinline__ void mma16816(float* c, const uint32_t* a, const uint32_t* b) {
    asm volatile("mma.sync.aligned.m16n8k16.row.col.f32.bf16.bf16.f32 "
        "{%0,%1,%2,%3}, {%4,%5,%6,%7}, {%8,%9}, {%0,%1,%2,%3};"
        : "+f"(c[0]), "+f"(c[1]), "+f"(c[2]), "+f"(c[3])
        : "r"(a[0]), "r"(a[1]), "r"(a[2]), "r"(a[3]), "r"(b[0]), "r"(b[1]));
}

// ---------------- preprocessing ----------------
__global__ void k_detect(const void* ei) {
    const unsigned int* p = (const unsigned int*)ei;
    int ok64 = 1;
    for (int i = threadIdx.x; i < 64; i += 32)
        if (p[2 * i + 1] != 0u) ok64 = 0;
    ok64 = __all_sync(0xffffffffu, ok64);
    if (threadIdx.x == 0) g_is64 = ok64;
}

__global__ void k_init_cnt() {
    int i = blockIdx.x * blockDim.x + threadIdx.x;
    if (i < NN) g_cnt[i] = 0;
}

__global__ void k_invnorm(const float* __restrict__ feats) {
    int w = (blockIdx.x * blockDim.x + threadIdx.x) >> 5;
    int lane = threadIdx.x & 31;
    if (w >= NN) return;
    const float4* p = (const float4*)(feats + (size_t)w * KIN);
    float ss = 0.f;
#pragma unroll
    for (int i = 0; i < 4; ++i) {
        float4 v = p[i * 32 + lane];
        ss += v.x * v.x + v.y * v.y + v.z * v.z + v.w * v.w;
    }
#pragma unroll
    for (int o = 16; o > 0; o >>= 1) ss += __shfl_xor_sync(0xffffffffu, ss, o);
    if (lane == 0) g_invnorm[w] = 1.0f / fmaxf(sqrtf(ss), 1e-12f);
}

__global__ void k_count(const void* ei) {
    int e = blockIdx.x * blockDim.x + threadIdx.x;
    if (e >= EE) return;
    int r, c;
    if (g_is64) {
        const long long* p = (const long long*)ei;
        r = (int)p[e]; c = (int)p[EE + e];
    } else {
        const int* p = (const int*)ei;
        r = p[e]; c = p[EE + e];
    }
    g_erow[e] = r;
    g_ecol0[e] = c;
    atomicAdd(&g_cnt[r], 1);
}

__global__ void k_scan1() {
    __shared__ int sm[1024];
    int t = threadIdx.x;
    int i = blockIdx.x * 1024 + t;
    int v = (i < NN) ? g_cnt[i] : 0;
    sm[t] = v;
    __syncthreads();
    for (int d = 1; d < 1024; d <<= 1) {
        int add = (t >= d) ? sm[t - d] : 0;
        __syncthreads();
        sm[t] += add;
        __syncthreads();
    }
    int incl = sm[t];
    if (i < NN) g_off[i] = incl - v;
    if (t == 1023) g_bsum[blockIdx.x] = incl;
}

__global__ void k_scan2() {
    __shared__ int sm[128];
    int t = threadIdx.x;
    int v = (t < NBLK) ? g_bsum[t] : 0;
    sm[t] = v;
    __syncthreads();
    for (int d = 1; d < 128; d <<= 1) {
        int add = (t >= d) ? sm[t - d] : 0;
        __syncthreads();
        sm[t] += add;
        __syncthreads();
    }
    g_boff[t] = sm[t] - v;
}

__global__ void k_scan3() {
    int t = threadIdx.x;
    int i = blockIdx.x * 1024 + t;
    if (i < NN) {
        int off = g_off[i] + g_boff[blockIdx.x];
        g_off[i] = off;
        g_cursor[i] = off;
        g_dinv[i] = rsqrtf((float)(g_cnt[i] + 1));
        if (i == 0) g_off[NN] = EE;
    }
}

__global__ void k_scatter() {
    int e = blockIdx.x * blockDim.x + threadIdx.x;
    if (e >= EE) return;
    int r = g_erow[e], c = g_ecol0[e];
    int pos = atomicAdd(&g_cursor[r], 1);
    g_ecol[pos] = c;
    g_ew[pos] = g_dinv[r] * g_dinv[c];
}

// weight transpose + split: out[m][n][k] = W[m][k][n]
__global__ void k_wprep(const float* __restrict__ W, bf16* __restrict__ hi,
                        bf16* __restrict__ lo, int K, int total) {
    int o = blockIdx.x * blockDim.x + threadIdx.x;
    if (o >= total) return;
    int k = o % K;
    int rem = o / K;
    int n = rem % HF;
    int m = rem / HF;
    float x = W[(size_t)m * K * HF + (size_t)k * HF + n];
    bf16 h = __float2bfloat16(x);
    hi[o] = h;
    lo[o] = __float2bfloat16(x - __bfloat162float(h));
}

// warp-per-node SpMM with self-loop, CSR, register accumulation (no atomics)
__global__ void k_spmm(const float* __restrict__ zin, float* __restrict__ zout) {
    int w = (blockIdx.x * blockDim.x + threadIdx.x) >> 5;
    int lane = threadIdx.x & 31;
    if (w >= NN) return;
    int s = g_off[w], e = g_off[w + 1];
    float dn = g_dinv[w];
    float ws = dn * dn;
    float4 acc = ((const float4*)(zin + (size_t)w * HF))[lane];
    acc.x *= ws; acc.y *= ws; acc.z *= ws; acc.w *= ws;
#pragma unroll 4
    for (int j = s; j < e; ++j) {
        int c = g_ecol[j];
        float wt = g_ew[j];
        float4 v = ((const float4*)(zin + (size_t)c * HF))[lane];
        acc.x += wt * v.x; acc.y += wt * v.y; acc.z += wt * v.z; acc.w += wt * v.w;
    }
    ((float4*)(zout + (size_t)w * HF))[lane] = acc;
}

// ---------------- HMMA bf16 3-term GEMM + bias + LayerNorm + ReLU ----------------
// smem map: [0,1536) bias|gamma|beta, tiles at 2048; epilogue scratch aliases tile A
#define OFF_PAR 0
#define TILE_B  (128 * ASTR * 2)      // 18432
#define OFF_AH  2048
#define OFF_AL  (OFF_AH + TILE_B)
#define OFF_BH  (OFF_AH + 2 * TILE_B)
#define OFF_BL  (OFF_AH + 3 * TILE_B)
#define SMEM_DYN (OFF_AH + 4 * TILE_B)   // 75776

template <int K>
__global__ __launch_bounds__(256, 2)
void k_mma(const float* __restrict__ A, int lda, const float* __restrict__ rowscale,
           const bf16* __restrict__ Whi, const bf16* __restrict__ Wlo,
           const float* __restrict__ bias, const float* __restrict__ gamma,
           const float* __restrict__ beta,
           float* __restrict__ C, int ldc, int noff)
{
    extern __shared__ char smem[];
    bf16* sAh = (bf16*)(smem + OFF_AH);
    bf16* sAl = (bf16*)(smem + OFF_AL);
    bf16* sBh = (bf16*)(smem + OFF_BH);
    bf16* sBl = (bf16*)(smem + OFF_BL);
    uint32_t sbase = smem_to_u32(smem);

    const int t = threadIdx.x, lane = t & 31, wid = t >> 5;
    const int warp_m = wid & 1, warp_n = wid >> 1;   // 2 (M) x 4 (N)
    const int m0 = blockIdx.x * 128;

    // params to smem
    if (t < 128) {
        ((float*)(smem + OFF_PAR))[t]       = bias[t];
        ((float*)(smem + OFF_PAR))[128 + t] = gamma[t];
        ((float*)(smem + OFF_PAR))[256 + t] = beta[t];
    }

    float acc[4][4][4];
#pragma unroll
    for (int i = 0; i < 4; ++i)
#pragma unroll
        for (int j = 0; j < 4; ++j)
#pragma unroll
            for (int u = 0; u < 4; ++u) acc[i][j][u] = 0.f;

    // ldmatrix lane addressing
    const int a_row = warp_m * 64 + (lane & 7) + ((lane >> 3) & 1) * 8;
    const int a_col = (lane >> 4) * 8;
    const int b_row = warp_n * 32 + (lane & 7);
    const int b_col = ((lane >> 3) & 1) * 8;

    for (int k0 = 0; k0 < K; k0 += BK) {
        // ---- stage A (fp32 -> hi/lo bf16) and B (pre-split bf16) ----
        for (int i = t; i < 2048; i += 256) {
            int row = i >> 4, cq = (i & 15) * 4;
            float4 v = make_float4(0.f, 0.f, 0.f, 0.f);
            int gm = m0 + row;
            if (gm < NN) {
                v = *(const float4*)(A + (size_t)gm * lda + k0 + cq);
                if (rowscale) {
                    float sc = rowscale[gm];
                    v.x *= sc; v.y *= sc; v.z *= sc; v.w *= sc;
                }
            }
            uint2 H, L;
            split2(v.x, v.y, H.x, L.x);
            split2(v.z, v.w, H.y, L.y);
            *(uint2*)(sAh + row * ASTR + cq) = H;
            *(uint2*)(sAl + row * ASTR + cq) = L;
            *(uint2*)(sBh + row * ASTR + cq) = *(const uint2*)(Whi + (size_t)row * K + k0 + cq);
            *(uint2*)(sBl + row * ASTR + cq) = *(const uint2*)(Wlo + (size_t)row * K + k0 + cq);
        }
        __syncthreads();

#pragma unroll
        for (int kk = 0; kk < BK; kk += 16) {
            uint32_t bh[4][2], bl[4][2];
#pragma unroll
            for (int nt = 0; nt < 4; ++nt) {
                uint32_t boff = (uint32_t)(((b_row + nt * 8) * ASTR + kk + b_col) * 2);
                ldsm2(bh[nt], sbase + OFF_BH + boff);
                ldsm2(bl[nt], sbase + OFF_BL + boff);
            }
#pragma unroll
            for (int mt = 0; mt < 4; ++mt) {
                uint32_t ah[4], al[4];
                uint32_t aoff = (uint32_t)(((a_row + mt * 16) * ASTR + kk + a_col) * 2);
                ldsm4(ah, sbase + OFF_AH + aoff);
                ldsm4(al, sbase + OFF_AL + aoff);
#pragma unroll
                for (int nt = 0; nt < 4; ++nt) {
                    mma16816(acc[mt][nt], ah, bh[nt]);
                    mma16816(acc[mt][nt], ah, bl[nt]);
                    mma16816(acc[mt][nt], al, bh[nt]);
                }
            }
        }
        __syncthreads();
    }

    // ---- epilogue in registers ----
    const float* pb = (const float*)(smem + OFF_PAR);
    const float* pg = pb + 128;
    const float* pe = pb + 256;
    float* s_sum = (float*)(smem + OFF_AH);       // [4][128], aliases dead tile A
    float* s_sq  = s_sum + 512;
    float* s_mu  = s_sq + 512;
    float* s_inv = s_mu + 128;

    // add bias into fragments
#pragma unroll
    for (int nt = 0; nt < 4; ++nt) {
        int c = warp_n * 32 + nt * 8 + (lane & 3) * 2;
        float b0 = pb[c], b1 = pb[c + 1];
#pragma unroll
        for (int mt = 0; mt < 4; ++mt) {
            acc[mt][nt][0] += b0; acc[mt][nt][1] += b1;
            acc[mt][nt][2] += b0; acc[mt][nt][3] += b1;
        }
    }
    // per-row partial sums over this warp's 32 columns
#pragma unroll
    for (int mt = 0; mt < 4; ++mt) {
#pragma unroll
        for (int rh = 0; rh < 2; ++rh) {
            float s = 0.f, q = 0.f;
#pragma unroll
            for (int nt = 0; nt < 4; ++nt) {
                float x0 = acc[mt][nt][2 * rh], x1 = acc[mt][nt][2 * rh + 1];
                s += x0 + x1;
                q += x0 * x0 + x1 * x1;
            }
            s += __shfl_xor_sync(0xffffffffu, s, 1);
            q += __shfl_xor_sync(0xffffffffu, q, 1);
            s += __shfl_xor_sync(0xffffffffu, s, 2);
            q += __shfl_xor_sync(0xffffffffu, q, 2);
            if ((lane & 3) == 0) {
                int r = warp_m * 64 + mt * 16 + (lane >> 2) + rh * 8;
                s_sum[warp_n * 128 + r] = s;
                s_sq [warp_n * 128 + r] = q;
            }
        }
    }
    __syncthreads();
    if (t < 128) {
        float s = s_sum[t] + s_sum[128 + t] + s_sum[256 + t] + s_sum[384 + t];
        float q = s_sq [t] + s_sq [128 + t] + s_sq [256 + t] + s_sq [384 + t];
        float mu  = s * (1.0f / 128.0f);
        float var = q * (1.0f / 128.0f) - mu * mu;
        s_mu[t]  = mu;
        s_inv[t] = rsqrtf(var + 1e-5f);
    }
    __syncthreads();
    // transform + store
#pragma unroll
    for (int mt = 0; mt < 4; ++mt) {
#pragma unroll
        for (int rh = 0; rh < 2; ++rh) {
            int r = warp_m * 64 + mt * 16 + (lane >> 2) + rh * 8;
            int gm = m0 + r;
            if (gm >= NN) continue;
            float mu = s_mu[r], inv = s_inv[r];
            float* cp = C + (size_t)gm * ldc + noff;
#pragma unroll
            for (int nt = 0; nt < 4; ++nt) {
                int c = warp_n * 32 + nt * 8 + (lane & 3) * 2;
                float2 y;
                y.x = fmaxf((acc[mt][nt][2 * rh]     - mu) * inv * pg[c]     + pe[c],     0.f);
                y.y = fmaxf((acc[mt][nt][2 * rh + 1] - mu) * inv * pg[c + 1] + pe[c + 1], 0.f);
                *(float2*)(cp + c) = y;
            }
        }
    }
}

// ---------------- launch ----------------
extern "C" void kernel_launch(void* const* d_in, const int* in_sizes, int n_in,
                              void* d_out, int out_size)
{
    const void*  ei     = d_in[0];
    const float* feats  = (const float*)d_in[1];
    const float* W_uni  = (const float*)d_in[2];
    const float* b_uni  = (const float*)d_in[3];
    const float* g_uni  = (const float*)d_in[4];
    const float* be_uni = (const float*)d_in[5];
    const float* W_ind  = (const float*)d_in[6];
    const float* b_ind  = (const float*)d_in[7];
    const float* g_ind  = (const float*)d_in[8];
    const float* be_ind = (const float*)d_in[9];
    const float* W_rel  = (const float*)d_in[10];
    const float* b_rel  = (const float*)d_in[11];
    const float* g_rel  = (const float*)d_in[12];
    const float* be_rel = (const float*)d_in[13];
    float* out = (float*)d_out;

    cudaFuncSetAttribute(k_mma<KIN>, cudaFuncAttributeMaxDynamicSharedMemorySize, SMEM_DYN);
    cudaFuncSetAttribute(k_mma<HF>,  cudaFuncAttributeMaxDynamicSharedMemorySize, SMEM_DYN);

    float *ph, *pza, *pzb, *pcat, *pinv;
    bf16 *pwuh, *pwul, *pwih, *pwil, *pwrh, *pwrl;
    cudaGetSymbolAddress((void**)&ph,   g_h);
    cudaGetSymbolAddress((void**)&pza,  g_za);
    cudaGetSymbolAddress((void**)&pzb,  g_zb);
    cudaGetSymbolAddress((void**)&pcat, g_cat);
    cudaGetSymbolAddress((void**)&pinv, g_invnorm);
    cudaGetSymbolAddress((void**)&pwuh, g_wu_hi);
    cudaGetSymbolAddress((void**)&pwul, g_wu_lo);
    cudaGetSymbolAddress((void**)&pwih, g_wi_hi);
    cudaGetSymbolAddress((void**)&pwil, g_wi_lo);
    cudaGetSymbolAddress((void**)&pwrh, g_wr_hi);
    cudaGetSymbolAddress((void**)&pwrl, g_wr_lo);

    // ---- graph preprocessing ----
    k_detect<<<1, 32>>>(ei);
    k_init_cnt<<<(NN + 255) / 256, 256>>>();
    k_invnorm<<<NN / 8, 256>>>(feats);
    k_count<<<(EE + 255) / 256, 256>>>(ei);
    k_scan1<<<NBLK, 1024>>>();
    k_scan2<<<1, 128>>>();
    k_scan3<<<NBLK, 1024>>>();
    k_scatter<<<(EE + 255) / 256, 256>>>();

    // ---- weight prep (transpose + bf16 hi/lo split) ----
    k_wprep<<<(HF * KIN + 255) / 256, 256>>>(W_uni, pwuh, pwul, KIN, HF * KIN);
    k_wprep<<<(4 * HF * HF + 255) / 256, 256>>>(W_ind, pwih, pwil, HF, 4 * HF * HF);
    k_wprep<<<(HF * KIN + 255) / 256, 256>>>(W_rel, pwrh, pwrl, KIN, HF * KIN);

    // ---- h = MLP_uni(normalize(feats)) ----
    k_mma<KIN><<<GRID_M, 256, SMEM_DYN>>>(feats, KIN, pinv, pwuh, pwul,
                                          b_uni, g_uni, be_uni, ph, HF, 0);
    // hop 0
    k_mma<HF><<<GRID_M, 256, SMEM_DYN>>>(ph, HF, nullptr, pwih, pwil,
                                         b_ind, g_ind, be_ind, pcat, 4 * HF, 0);
    // hop 1
    k_spmm<<<NN / 8, 256>>>(ph, pza);
    k_mma<HF><<<GRID_M, 256, SMEM_DYN>>>(pza, HF, nullptr,
                                         pwih + 1 * HF * HF, pwil + 1 * HF * HF,
                                         b_ind + 1 * HF, g_ind + 1 * HF, be_ind + 1 * HF,
                                         pcat, 4 * HF, 1 * HF);
    // hop 2
    k_spmm<<<NN / 8, 256>>>(pza, pzb);
    k_mma<HF><<<GRID_M, 256, SMEM_DYN>>>(pzb, HF, nullptr,
                                         pwih + 2 * HF * HF, pwil + 2 * HF * HF,
                                         b_ind + 2 * HF, g_ind + 2 * HF, be_ind + 2 * HF,
                                         pcat, 4 * HF, 2 * HF);
    // hop 3
    k_spmm<<<NN / 8, 256>>>(pzb, pza);
    k_mma<HF><<<GRID_M, 256, SMEM_DYN>>>(pza, HF, nullptr,
                                         pwih + 3 * HF * HF, pwil + 3 * HF * HF,
                                         b_ind + 3 * HF, g_ind + 3 * HF, be_ind + 3 * HF,
                                         pcat, 4 * HF, 3 * HF);
    // relation MLP -> d_out
    k_mma<KIN><<<GRID_M, 256, SMEM_DYN>>>(pcat, 4 * HF, nullptr, pwrh, pwrl,
                                          b_rel, g_rel, be_rel, out, HF, 0);
}

// round 6
// speedup vs baseline: 1.8481x; 1.0641x over previous
#include <cuda_runtime.h>
#include <cuda_bf16.h>
#include <cstdint>
#include <cstddef>

#define NN 100000
#define EE 1600000
#define HF 128
#define KIN 512
#define NBLK 98     // ceil(NN/1024)
#define GRID_M 782  // ceil(NN/128)
#define BK 64
#define ASTR 72     // padded smem row stride (bf16 elems): 144B rows -> conflict-free LDSM

typedef __nv_bfloat16 bf16;

// ---------------- scratch (static device globals; no allocations) ----------------
__device__ int   g_is64;
__device__ float g_invnorm[NN];
__device__ int   g_cnt[NN];
__device__ float g_dinv[NN];
__device__ int   g_erow[EE];
__device__ int   g_ecol0[EE];
__device__ int   g_off[NN + 1];
__device__ int   g_cursor[NN];
__device__ int   g_bsum[128];
__device__ int   g_boff[128];
__device__ int   g_ecol[EE];
__device__ float g_ew[EE];

__device__ float g_h  [(size_t)NN * HF];
__device__ float g_za [(size_t)NN * HF];
__device__ float g_zb [(size_t)NN * HF];
__device__ float g_zc [(size_t)NN * HF];
__device__ float g_cat[(size_t)NN * 4 * HF];

// transposed + hi/lo split weights: Wt[n][k] = W[k][n]
__device__ bf16 g_wu_hi[HF * KIN];
__device__ bf16 g_wu_lo[HF * KIN];
__device__ bf16 g_wi_hi[4 * HF * HF];
__device__ bf16 g_wi_lo[4 * HF * HF];
__device__ bf16 g_wr_hi[HF * KIN];
__device__ bf16 g_wr_lo[HF * KIN];

// ---------------- helpers ----------------
__device__ __forceinline__ uint32_t smem_to_u32(const void* p) {
    uint32_t a;
    asm("{ .reg .u64 t; cvta.to.shared.u64 t, %1; cvt.u32.u64 %0, t; }" : "=r"(a) : "l"(p));
    return a;
}
__device__ __forceinline__ uint32_t bpack(bf16 a, bf16 b) {
    __nv_bfloat162 t(a, b);
    return *reinterpret_cast<uint32_t*>(&t);
}
__device__ __forceinline__ void split2(float a, float b, uint32_t& hi, uint32_t& lo) {
    bf16 ha = __float2bfloat16(a), hb = __float2bfloat16(b);
    float ra = a - __bfloat162float(ha);
    float rb = b - __bfloat162float(hb);
    hi = bpack(ha, hb);
    lo = bpack(__float2bfloat16(ra), __float2bfloat16(rb));
}
__device__ __forceinline__ void ldsm4(uint32_t* r, uint32_t a) {
    asm volatile("ldmatrix.sync.aligned.m8n8.x4.shared.b16 {%0,%1,%2,%3}, [%4];"
        : "=r"(r[0]), "=r"(r[1]), "=r"(r[2]), "=r"(r[3]) : "r"(a));
}
__device__ __forceinline__ void ldsm2(uint32_t* r, uint32_t a) {
    asm volatile("ldmatrix.sync.aligned.m8n8.x2.shared.b16 {%0,%1}, [%2];"
        : "=r"(r[0]), "=r"(r[1]) : "r"(a));
}
__device__ __forceinline__ void mma16816(float* c, const uint32_t* a, const uint32_t* b) {
    asm volatile("mma.sync.aligned.m16n8k16.row.col.f32.bf16.bf16.f32 "
        "{%0,%1,%2,%3}, {%4,%5,%6,%7}, {%8,%9}, {%0,%1,%2,%3};"
        : "+f"(c[0]), "+f"(c[1]), "+f"(c[2]), "+f"(c[3])
        : "r"(a[0]), "r"(a[1]), "r"(a[2]), "r"(a[3]), "r"(b[0]), "r"(b[1]));
}

// ---------------- preprocessing ----------------
__global__ void k_detect(const void* ei) {
    const unsigned int* p = (const unsigned int*)ei;
    int ok64 = 1;
    for (int i = threadIdx.x; i < 64; i += 32)
        if (p[2 * i + 1] != 0u) ok64 = 0;
    ok64 = __all_sync(0xffffffffu, ok64);
    if (threadIdx.x == 0) g_is64 = ok64;
}

__global__ void k_init_cnt() {
    int i = blockIdx.x * blockDim.x + threadIdx.x;
    if (i < NN) g_cnt[i] = 0;
}

__global__ void k_invnorm(const float* __restrict__ feats) {
    int w = (blockIdx.x * blockDim.x + threadIdx.x) >> 5;
    int lane = threadIdx.x & 31;
    if (w >= NN) return;
    const float4* p = (const float4*)(feats + (size_t)w * KIN);
    float ss = 0.f;
#pragma unroll
    for (int i = 0; i < 4; ++i) {
        float4 v = p[i * 32 + lane];
        ss += v.x * v.x + v.y * v.y + v.z * v.z + v.w * v.w;
    }
#pragma unroll
    for (int o = 16; o > 0; o >>= 1) ss += __shfl_xor_sync(0xffffffffu, ss, o);
    if (lane == 0) g_invnorm[w] = 1.0f / fmaxf(sqrtf(ss), 1e-12f);
}

__global__ void k_count(const void* ei) {
    int e = blockIdx.x * blockDim.x + threadIdx.x;
    if (e >= EE) return;
    int r, c;
    if (g_is64) {
        const long long* p = (const long long*)ei;
        r = (int)p[e]; c = (int)p[EE + e];
    } else {
        const int* p = (const int*)ei;
        r = p[e]; c = p[EE + e];
    }
    g_erow[e] = r;
    g_ecol0[e] = c;
    atomicAdd(&g_cnt[r], 1);
}

__global__ void k_scan1() {
    __shared__ int sm[1024];
    int t = threadIdx.x;
    int i = blockIdx.x * 1024 + t;
    int v = (i < NN) ? g_cnt[i] : 0;
    sm[t] = v;
    __syncthreads();
    for (int d = 1; d < 1024; d <<= 1) {
        int add = (t >= d) ? sm[t - d] : 0;
        __syncthreads();
        sm[t] += add;
        __syncthreads();
    }
    int incl = sm[t];
    if (i < NN) g_off[i] = incl - v;
    if (t == 1023) g_bsum[blockIdx.x] = incl;
}

__global__ void k_scan2() {
    __shared__ int sm[128];
    int t = threadIdx.x;
    int v = (t < NBLK) ? g_bsum[t] : 0;
    sm[t] = v;
    __syncthreads();
    for (int d = 1; d < 128; d <<= 1) {
        int add = (t >= d) ? sm[t - d] : 0;
        __syncthreads();
        sm[t] += add;
        __syncthreads();
    }
    g_boff[t] = sm[t] - v;
}

__global__ void k_scan3() {
    int t = threadIdx.x;
    int i = blockIdx.x * 1024 + t;
    if (i < NN) {
        int off = g_off[i] + g_boff[blockIdx.x];
        g_off[i] = off;
        g_cursor[i] = off;
        g_dinv[i] = rsqrtf((float)(g_cnt[i] + 1));
        if (i == 0) g_off[NN] = EE;
    }
}

__global__ void k_scatter() {
    int e = blockIdx.x * blockDim.x + threadIdx.x;
    if (e >= EE) return;
    int r = g_erow[e], c = g_ecol0[e];
    int pos = atomicAdd(&g_cursor[r], 1);
    g_ecol[pos] = c;
    g_ew[pos] = g_dinv[r] * g_dinv[c];
}

// weight transpose + split: out[m][n][k] = W[m][k][n]
__global__ void k_wprep(const float* __restrict__ W, bf16* __restrict__ hi,
                        bf16* __restrict__ lo, int K, int total) {
    int o = blockIdx.x * blockDim.x + threadIdx.x;
    if (o >= total) return;
    int k = o % K;
    int rem = o / K;
    int n = rem % HF;
    int m = rem / HF;
    float x = W[(size_t)m * K * HF + (size_t)k * HF + n];
    bf16 h = __float2bfloat16(x);
    hi[o] = h;
    lo[o] = __float2bfloat16(x - __bfloat162float(h));
}

// warp-per-node SpMM with self-loop, CSR, register accumulation (no atomics)
__global__ void k_spmm(const float* __restrict__ zin, float* __restrict__ zout) {
    int w = (blockIdx.x * blockDim.x + threadIdx.x) >> 5;
    int lane = threadIdx.x & 31;
    if (w >= NN) return;
    int s = g_off[w], e = g_off[w + 1];
    float dn = g_dinv[w];
    float ws = dn * dn;
    float4 acc = ((const float4*)(zin + (size_t)w * HF))[lane];
    acc.x *= ws; acc.y *= ws; acc.z *= ws; acc.w *= ws;
#pragma unroll 4
    for (int j = s; j < e; ++j) {
        int c = g_ecol[j];
        float wt = g_ew[j];
        float4 v = ((const float4*)(zin + (size_t)c * HF))[lane];
        acc.x += wt * v.x; acc.y += wt * v.y; acc.z += wt * v.z; acc.w += wt * v.w;
    }
    ((float4*)(zout + (size_t)w * HF))[lane] = acc;
}

// ---------------- HMMA bf16 3-term GEMM + bias + LayerNorm + ReLU ----------------
#define OFF_PAR 0
#define TILE_B  (128 * ASTR * 2)      // 18432
#define OFF_AH  2048
#define OFF_AL  (OFF_AH + TILE_B)
#define OFF_BH  (OFF_AH + 2 * TILE_B)
#define OFF_BL  (OFF_AH + 3 * TILE_B)
#define SMEM_DYN (OFF_AH + 4 * TILE_B)   // 75776

template <int K>
__global__ __launch_bounds__(256, 2)
void k_mma(const float* __restrict__ A, int lda, const float* __restrict__ rowscale,
           const bf16* __restrict__ Whi, const bf16* __restrict__ Wlo,
           const float* __restrict__ bias, const float* __restrict__ gamma,
           const float* __restrict__ beta,
           float* __restrict__ C, int ldc, int noff)
{
    extern __shared__ char smem[];
    bf16* sAh = (bf16*)(smem + OFF_AH);
    bf16* sAl = (bf16*)(smem + OFF_AL);
    bf16* sBh = (bf16*)(smem + OFF_BH);
    bf16* sBl = (bf16*)(smem + OFF_BL);
    uint32_t sbase = smem_to_u32(smem);

    const int t = threadIdx.x, lane = t & 31, wid = t >> 5;
    const int warp_m = wid & 1, warp_n = wid >> 1;   // 2 (M) x 4 (N)
    const int m0 = blockIdx.x * 128;

    if (t < 128) {
        ((float*)(smem + OFF_PAR))[t]       = bias[t];
        ((float*)(smem + OFF_PAR))[128 + t] = gamma[t];
        ((float*)(smem + OFF_PAR))[256 + t] = beta[t];
    }

    float acc[4][4][4];
#pragma unroll
    for (int i = 0; i < 4; ++i)
#pragma unroll
        for (int j = 0; j < 4; ++j)
#pragma unroll
            for (int u = 0; u < 4; ++u) acc[i][j][u] = 0.f;

    const int a_row = warp_m * 64 + (lane & 7) + ((lane >> 3) & 1) * 8;
    const int a_col = (lane >> 4) * 8;
    const int b_row = warp_n * 32 + (lane & 7);
    const int b_col = ((lane >> 3) & 1) * 8;

    for (int k0 = 0; k0 < K; k0 += BK) {
        for (int i = t; i < 2048; i += 256) {
            int row = i >> 4, cq = (i & 15) * 4;
            float4 v = make_float4(0.f, 0.f, 0.f, 0.f);
            int gm = m0 + row;
            if (gm < NN) {
                v = *(const float4*)(A + (size_t)gm * lda + k0 + cq);
                if (rowscale) {
                    float sc = rowscale[gm];
                    v.x *= sc; v.y *= sc; v.z *= sc; v.w *= sc;
                }
            }
            uint2 H, L;
            split2(v.x, v.y, H.x, L.x);
            split2(v.z, v.w, H.y, L.y);
            *(uint2*)(sAh + row * ASTR + cq) = H;
            *(uint2*)(sAl + row * ASTR + cq) = L;
            *(uint2*)(sBh + row * ASTR + cq) = *(const uint2*)(Whi + (size_t)row * K + k0 + cq);
            *(uint2*)(sBl + row * ASTR + cq) = *(const uint2*)(Wlo + (size_t)row * K + k0 + cq);
        }
        __syncthreads();

#pragma unroll
        for (int kk = 0; kk < BK; kk += 16) {
            uint32_t bh[4][2], bl[4][2];
#pragma unroll
            for (int nt = 0; nt < 4; ++nt) {
                uint32_t boff = (uint32_t)(((b_row + nt * 8) * ASTR + kk + b_col) * 2);
                ldsm2(bh[nt], sbase + OFF_BH + boff);
                ldsm2(bl[nt], sbase + OFF_BL + boff);
            }
#pragma unroll
            for (int mt = 0; mt < 4; ++mt) {
                uint32_t ah[4], al[4];
                uint32_t aoff = (uint32_t)(((a_row + mt * 16) * ASTR + kk + a_col) * 2);
                ldsm4(ah, sbase + OFF_AH + aoff);
                ldsm4(al, sbase + OFF_AL + aoff);
#pragma unroll
                for (int nt = 0; nt < 4; ++nt) {
                    mma16816(acc[mt][nt], ah, bh[nt]);
                    mma16816(acc[mt][nt], ah, bl[nt]);
                    mma16816(acc[mt][nt], al, bh[nt]);
                }
            }
        }
        __syncthreads();
    }

    // ---- epilogue in registers ----
    const float* pb = (const float*)(smem + OFF_PAR);
    const float* pg = pb + 128;
    const float* pe = pb + 256;
    float* s_sum = (float*)(smem + OFF_AH);
    float* s_sq  = s_sum + 512;
    float* s_mu  = s_sq + 512;
    float* s_inv = s_mu + 128;

#pragma unroll
    for (int nt = 0; nt < 4; ++nt) {
        int c = warp_n * 32 + nt * 8 + (lane & 3) * 2;
        float b0 = pb[c], b1 = pb[c + 1];
#pragma unroll
        for (int mt = 0; mt < 4; ++mt) {
            acc[mt][nt][0] += b0; acc[mt][nt][1] += b1;
            acc[mt][nt][2] += b0; acc[mt][nt][3] += b1;
        }
    }
#pragma unroll
    for (int mt = 0; mt < 4; ++mt) {
#pragma unroll
        for (int rh = 0; rh < 2; ++rh) {
            float s = 0.f, q = 0.f;
#pragma unroll
            for (int nt = 0; nt < 4; ++nt) {
                float x0 = acc[mt][nt][2 * rh], x1 = acc[mt][nt][2 * rh + 1];
                s += x0 + x1;
                q += x0 * x0 + x1 * x1;
            }
            s += __shfl_xor_sync(0xffffffffu, s, 1);
            q += __shfl_xor_sync(0xffffffffu, q, 1);
            s += __shfl_xor_sync(0xffffffffu, s, 2);
            q += __shfl_xor_sync(0xffffffffu, q, 2);
            if ((lane & 3) == 0) {
                int r = warp_m * 64 + mt * 16 + (lane >> 2) + rh * 8;
                s_sum[warp_n * 128 + r] = s;
                s_sq [warp_n * 128 + r] = q;
            }
        }
    }
    __syncthreads();
    if (t < 128) {
        float s = s_sum[t] + s_sum[128 + t] + s_sum[256 + t] + s_sum[384 + t];
        float q = s_sq [t] + s_sq [128 + t] + s_sq [256 + t] + s_sq [384 + t];
        float mu  = s * (1.0f / 128.0f);
        float var = q * (1.0f / 128.0f) - mu * mu;
        s_mu[t]  = mu;
        s_inv[t] = rsqrtf(var + 1e-5f);
    }
    __syncthreads();
#pragma unroll
    for (int mt = 0; mt < 4; ++mt) {
#pragma unroll
        for (int rh = 0; rh < 2; ++rh) {
            int r = warp_m * 64 + mt * 16 + (lane >> 2) + rh * 8;
            int gm = m0 + r;
            if (gm >= NN) continue;
            float mu = s_mu[r], inv = s_inv[r];
            float* cp = C + (size_t)gm * ldc + noff;
#pragma unroll
            for (int nt = 0; nt < 4; ++nt) {
                int c = warp_n * 32 + nt * 8 + (lane & 3) * 2;
                float2 y;
                y.x = fmaxf((acc[mt][nt][2 * rh]     - mu) * inv * pg[c]     + pe[c],     0.f);
                y.y = fmaxf((acc[mt][nt][2 * rh + 1] - mu) * inv * pg[c + 1] + pe[c + 1], 0.f);
                *(float2*)(cp + c) = y;
            }
        }
    }
}

// ---------------- launch ----------------
extern "C" void kernel_launch(void* const* d_in, const int* in_sizes, int n_in,
                              void* d_out, int out_size)
{
    const void*  ei     = d_in[0];
    const float* feats  = (const float*)d_in[1];
    const float* W_uni  = (const float*)d_in[2];
    const float* b_uni  = (const float*)d_in[3];
    const float* g_uni  = (const float*)d_in[4];
    const float* be_uni = (const float*)d_in[5];
    const float* W_ind  = (const float*)d_in[6];
    const float* b_ind  = (const float*)d_in[7];
    const float* g_ind  = (const float*)d_in[8];
    const float* be_ind = (const float*)d_in[9];
    const float* W_rel  = (const float*)d_in[10];
    const float* b_rel  = (const float*)d_in[11];
    const float* g_rel  = (const float*)d_in[12];
    const float* be_rel = (const float*)d_in[13];
    float* out = (float*)d_out;

    cudaFuncSetAttribute(k_mma<KIN>, cudaFuncAttributeMaxDynamicSharedMemorySize, SMEM_DYN);
    cudaFuncSetAttribute(k_mma<HF>,  cudaFuncAttributeMaxDynamicSharedMemorySize, SMEM_DYN);

    float *ph, *pza, *pzb, *pzc, *pcat, *pinv;
    bf16 *pwuh, *pwul, *pwih, *pwil, *pwrh, *pwrl;
    cudaGetSymbolAddress((void**)&ph,   g_h);
    cudaGetSymbolAddress((void**)&pza,  g_za);
    cudaGetSymbolAddress((void**)&pzb,  g_zb);
    cudaGetSymbolAddress((void**)&pzc,  g_zc);
    cudaGetSymbolAddress((void**)&pcat, g_cat);
    cudaGetSymbolAddress((void**)&pinv, g_invnorm);
    cudaGetSymbolAddress((void**)&pwuh, g_wu_hi);
    cudaGetSymbolAddress((void**)&pwul, g_wu_lo);
    cudaGetSymbolAddress((void**)&pwih, g_wi_hi);
    cudaGetSymbolAddress((void**)&pwil, g_wi_lo);
    cudaGetSymbolAddress((void**)&pwrh, g_wr_hi);
    cudaGetSymbolAddress((void**)&pwrl, g_wr_lo);

    // second stream + fork/join events (host objects only; created per call)
    cudaStream_t s2;
    cudaStreamCreateWithFlags(&s2, cudaStreamNonBlocking);
    cudaEvent_t evStart, evH, evZa, evZb, evZc, evDone;
    cudaEventCreateWithFlags(&evStart, cudaEventDisableTiming);
    cudaEventCreateWithFlags(&evH,     cudaEventDisableTiming);
    cudaEventCreateWithFlags(&evZa,    cudaEventDisableTiming);
    cudaEventCreateWithFlags(&evZb,    cudaEventDisableTiming);
    cudaEventCreateWithFlags(&evZc,    cudaEventDisableTiming);
    cudaEventCreateWithFlags(&evDone,  cudaEventDisableTiming);

    // fork s2 off the (captured) default stream
    cudaEventRecord(evStart, 0);
    cudaStreamWaitEvent(s2, evStart, 0);

    // ---- main stream: CSR build chain ----
    k_detect<<<1, 32>>>(ei);
    k_init_cnt<<<(NN + 255) / 256, 256>>>();
    k_count<<<(EE + 255) / 256, 256>>>(ei);
    k_scan1<<<NBLK, 1024>>>();
    k_scan2<<<1, 128>>>();
    k_scan3<<<NBLK, 1024>>>();
    k_scatter<<<(EE + 255) / 256, 256>>>();

    // ---- s2: dense chain (invnorm -> weights -> uni GEMM -> hop0) ----
    k_invnorm<<<NN / 8, 256, 0, s2>>>(feats);
    k_wprep<<<(HF * KIN + 255) / 256, 256, 0, s2>>>(W_uni, pwuh, pwul, KIN, HF * KIN);
    k_wprep<<<(4 * HF * HF + 255) / 256, 256, 0, s2>>>(W_ind, pwih, pwil, HF, 4 * HF * HF);
    k_wprep<<<(HF * KIN + 255) / 256, 256, 0, s2>>>(W_rel, pwrh, pwrl, KIN, HF * KIN);
    k_mma<KIN><<<GRID_M, 256, SMEM_DYN, s2>>>(feats, KIN, pinv, pwuh, pwul,
                                              b_uni, g_uni, be_uni, ph, HF, 0);
    cudaEventRecord(evH, s2);
    k_mma<HF><<<GRID_M, 256, SMEM_DYN, s2>>>(ph, HF, nullptr, pwih, pwil,
                                             b_ind, g_ind, be_ind, pcat, 4 * HF, 0);

    // ---- main: SpMM chain (needs CSR + h), overlapped with hop GEMMs on s2 ----
    cudaStreamWaitEvent(0, evH, 0);
    k_spmm<<<NN / 8, 256>>>(ph, pza);
    cudaEventRecord(evZa, 0);
    k_spmm<<<NN / 8, 256>>>(pza, pzb);
    cudaEventRecord(evZb, 0);
    k_spmm<<<NN / 8, 256>>>(pzb, pzc);
    cudaEventRecord(evZc, 0);

    // ---- s2: hop GEMMs as their inputs land ----
    cudaStreamWaitEvent(s2, evZa, 0);
    k_mma<HF><<<GRID_M, 256, SMEM_DYN, s2>>>(pza, HF, nullptr,
                                             pwih + 1 * HF * HF, pwil + 1 * HF * HF,
                                             b_ind + 1 * HF, g_ind + 1 * HF, be_ind + 1 * HF,
                                             pcat, 4 * HF, 1 * HF);
    cudaStreamWaitEvent(s2, evZb, 0);
    k_mma<HF><<<GRID_M, 256, SMEM_DYN, s2>>>(pzb, HF, nullptr,
                                             pwih + 2 * HF * HF, pwil + 2 * HF * HF,
                                             b_ind + 2 * HF, g_ind + 2 * HF, be_ind + 2 * HF,
                                             pcat, 4 * HF, 2 * HF);
    cudaStreamWaitEvent(s2, evZc, 0);
    k_mma<HF><<<GRID_M, 256, SMEM_DYN, s2>>>(pzc, HF, nullptr,
                                             pwih + 3 * HF * HF, pwil + 3 * HF * HF,
                                             b_ind + 3 * HF, g_ind + 3 * HF, be_ind + 3 * HF,
                                             pcat, 4 * HF, 3 * HF);
    // relation MLP -> d_out (s2, after all 4 hop GEMMs which are serial on s2)
    k_mma<KIN><<<GRID_M, 256, SMEM_DYN, s2>>>(pcat, 4 * HF, nullptr, pwrh, pwrl,
                                              b_rel, g_rel, be_rel, out, HF, 0);
    cudaEventRecord(evDone, s2);

    // join
    cudaStreamWaitEvent(0, evDone, 0);
}

// round 8
// speedup vs baseline: 1.8557x; 1.0041x over previous
#include <cuda_runtime.h>
#include <cuda_bf16.h>
#include <cstdint>
#include <cstddef>

#define NN 100000
#define EE 1600000
#define HF 128
#define KIN 512
#define NBLK 98     // ceil(NN/1024)
#define GRID_M 782  // ceil(NN/128)
#define BK 64
#define ASTR 72     // padded smem row stride (bf16 elems)

typedef __nv_bfloat16 bf16;

// ---------------- scratch (static device globals; no allocations) ----------------
__device__ int   g_is64;
__device__ float g_invnorm[NN];
__device__ int   g_cnt[NN];
__device__ float g_dinv[NN];
__device__ int   g_erow[EE];
__device__ int   g_ecol0[EE];
__device__ int   g_off[NN + 1];
__device__ int   g_cursor[NN];
__device__ int   g_bsum[128];
__device__ int   g_boff[128];
__device__ int2  g_epk[EE];          // packed (col, w-bits)

__device__ float g_h  [(size_t)NN * HF];
__device__ float g_za [(size_t)NN * HF];
__device__ float g_zb [(size_t)NN * HF];
__device__ float g_zc [(size_t)NN * HF];
__device__ float g_cat[(size_t)NN * 4 * HF];

// transposed + hi/lo split weights: Wt[n][k] = W[k][n]
__device__ bf16 g_wu_hi[HF * KIN];
__device__ bf16 g_wu_lo[HF * KIN];
__device__ bf16 g_wi_hi[4 * HF * HF];
__device__ bf16 g_wi_lo[4 * HF * HF];
__device__ bf16 g_wr_hi[HF * KIN];
__device__ bf16 g_wr_lo[HF * KIN];

// ---------------- helpers ----------------
__device__ __forceinline__ uint32_t smem_to_u32(const void* p) {
    uint32_t a;
    asm("{ .reg .u64 t; cvta.to.shared.u64 t, %1; cvt.u32.u64 %0, t; }" : "=r"(a) : "l"(p));
    return a;
}
__device__ __forceinline__ uint32_t bpack(bf16 a, bf16 b) {
    __nv_bfloat162 t(a, b);
    return *reinterpret_cast<uint32_t*>(&t);
}
__device__ __forceinline__ void split2(float a, float b, uint32_t& hi, uint32_t& lo) {
    bf16 ha = __float2bfloat16(a), hb = __float2bfloat16(b);
    float ra = a - __bfloat162float(ha);
    float rb = b - __bfloat162float(hb);
    hi = bpack(ha, hb);
    lo = bpack(__float2bfloat16(ra), __float2bfloat16(rb));
}
__device__ __forceinline__ void ldsm4(uint32_t* r, uint32_t a) {
    asm volatile("ldmatrix.sync.aligned.m8n8.x4.shared.b16 {%0,%1,%2,%3}, [%4];"
        : "=r"(r[0]), "=r"(r[1]), "=r"(r[2]), "=r"(r[3]) : "r"(a));
}
__device__ __forceinline__ void ldsm2(uint32_t* r, uint32_t a) {
    asm volatile("ldmatrix.sync.aligned.m8n8.x2.shared.b16 {%0,%1}, [%2];"
        : "=r"(r[0]), "=r"(r[1]) : "r"(a));
}
__device__ __forceinline__ void mma16816(float* c, const uint32_t* a, const uint32_t* b) {
    asm volatile("mma.sync.aligned.m16n8k16.row.col.f32.bf16.bf16.f32 "
        "{%0,%1,%2,%3}, {%4,%5,%6,%7}, {%8,%9}, {%0,%1,%2,%3};"
        : "+f"(c[0]), "+f"(c[1]), "+f"(c[2]), "+f"(c[3])
        : "r"(a[0]), "r"(a[1]), "r"(a[2]), "r"(a[3]), "r"(b[0]), "r"(b[1]));
}

// ---------------- preprocessing ----------------
__global__ void k_detect(const void* ei) {
    const unsigned int* p = (const unsigned int*)ei;
    int ok64 = 1;
    for (int i = threadIdx.x; i < 64; i += 32)
        if (p[2 * i + 1] != 0u) ok64 = 0;
    ok64 = __all_sync(0xffffffffu, ok64);
    if (threadIdx.x == 0) g_is64 = ok64;
}

__global__ void k_init_cnt() {
    int i = blockIdx.x * blockDim.x + threadIdx.x;
    if (i < NN) g_cnt[i] = 0;
}

__global__ void k_invnorm(const float* __restrict__ feats) {
    int w = (blockIdx.x * blockDim.x + threadIdx.x) >> 5;
    int lane = threadIdx.x & 31;
    if (w >= NN) return;
    const float4* p = (const float4*)(feats + (size_t)w * KIN);
    float ss = 0.f;
#pragma unroll
    for (int i = 0; i < 4; ++i) {
        float4 v = p[i * 32 + lane];
        ss += v.x * v.x + v.y * v.y + v.z * v.z + v.w * v.w;
    }
#pragma unroll
    for (int o = 16; o > 0; o >>= 1) ss += __shfl_xor_sync(0xffffffffu, ss, o);
    if (lane == 0) g_invnorm[w] = 1.0f / fmaxf(sqrtf(ss), 1e-12f);
}

__global__ void k_count(const void* ei) {
    int e = blockIdx.x * blockDim.x + threadIdx.x;
    if (e >= EE) return;
    int r, c;
    if (g_is64) {
        const long long* p = (const long long*)ei;
        r = (int)p[e]; c = (int)p[EE + e];
    } else {
        const int* p = (const int*)ei;
        r = p[e]; c = p[EE + e];
    }
    g_erow[e] = r;
    g_ecol0[e] = c;
    atomicAdd(&g_cnt[r], 1);
}

__global__ void k_scan1() {
    __shared__ int sm[1024];
    int t = threadIdx.x;
    int i = blockIdx.x * 1024 + t;
    int v = (i < NN) ? g_cnt[i] : 0;
    sm[t] = v;
    __syncthreads();
    for (int d = 1; d < 1024; d <<= 1) {
        int add = (t >= d) ? sm[t - d] : 0;
        __syncthreads();
        sm[t] += add;
        __syncthreads();
    }
    int incl = sm[t];
    if (i < NN) g_off[i] = incl - v;
    if (t == 1023) g_bsum[blockIdx.x] = incl;
}

__global__ void k_scan2() {
    __shared__ int sm[128];
    int t = threadIdx.x;
    int v = (t < NBLK) ? g_bsum[t] : 0;
    sm[t] = v;
    __syncthreads();
    for (int d = 1; d < 128; d <<= 1) {
        int add = (t >= d) ? sm[t - d] : 0;
        __syncthreads();
        sm[t] += add;
        __syncthreads();
    }
    g_boff[t] = sm[t] - v;
}

__global__ void k_scan3() {
    int t = threadIdx.x;
    int i = blockIdx.x * 1024 + t;
    if (i < NN) {
        int off = g_off[i] + g_boff[blockIdx.x];
        g_off[i] = off;
        g_cursor[i] = off;
        g_dinv[i] = rsqrtf((float)(g_cnt[i] + 1));
        if (i == 0) g_off[NN] = EE;
    }
}

__global__ void k_scatter() {
    int e = blockIdx.x * blockDim.x + threadIdx.x;
    if (e >= EE) return;
    int r = g_erow[e], c = g_ecol0[e];
    int pos = atomicAdd(&g_cursor[r], 1);
    g_epk[pos] = make_int2(c, __float_as_int(g_dinv[r] * g_dinv[c]));
}

// weight transpose + split: out[m][n][k] = W[m][k][n]
__global__ void k_wprep(const float* __restrict__ W, bf16* __restrict__ hi,
                        bf16* __restrict__ lo, int K, int total) {
    int o = blockIdx.x * blockDim.x + threadIdx.x;
    if (o >= total) return;
    int k = o % K;
    int rem = o / K;
    int n = rem % HF;
    int m = rem / HF;
    float x = W[(size_t)m * K * HF + (size_t)k * HF + n];
    bf16 h = __float2bfloat16(x);
    hi[o] = h;
    lo[o] = __float2bfloat16(x - __bfloat162float(h));
}

// warp-per-node SpMM with self-loop, CSR, register accumulation
__global__ void k_spmm(const float* __restrict__ zin, float* __restrict__ zout) {
    int w = (blockIdx.x * blockDim.x + threadIdx.x) >> 5;
    int lane = threadIdx.x & 31;
    if (w >= NN) return;
    int s = g_off[w], e = g_off[w + 1];
    float dn = g_dinv[w];
    float ws = dn * dn;
    float4 acc = ((const float4*)(zin + (size_t)w * HF))[lane];
    acc.x *= ws; acc.y *= ws; acc.z *= ws; acc.w *= ws;
#pragma unroll 4
    for (int j = s; j < e; ++j) {
        int2 e2 = g_epk[j];
        float wt = __int_as_float(e2.y);
        float4 v = ((const float4*)(zin + (size_t)e2.x * HF))[lane];
        acc.x += wt * v.x; acc.y += wt * v.y; acc.z += wt * v.z; acc.w += wt * v.w;
    }
    ((float4*)(zout + (size_t)w * HF))[lane] = acc;
}

// ---------------- HMMA bf16 3-term GEMM + bias + LayerNorm + ReLU ----------------
#define OFF_PAR 0
#define TILE_B  (128 * ASTR * 2)      // 18432
#define OFF_AH  2048
#define OFF_AL  (OFF_AH + TILE_B)
#define OFF_BH  (OFF_AH + 2 * TILE_B)
#define OFF_BL  (OFF_AH + 3 * TILE_B)
#define SMEM_DYN (OFF_AH + 4 * TILE_B)   // 75776

template <int K>
__global__ __launch_bounds__(256, 2)
void k_mma(const float* __restrict__ A, int lda, const float* __restrict__ rowscale,
           const bf16* __restrict__ Whi, const bf16* __restrict__ Wlo,
           const float* __restrict__ bias, const float* __restrict__ gamma,
           const float* __restrict__ beta,
           float* __restrict__ C, int ldc, int noff)
{
    extern __shared__ char smem[];
    bf16* sAh = (bf16*)(smem + OFF_AH);
    bf16* sAl = (bf16*)(smem + OFF_AL);
    bf16* sBh = (bf16*)(smem + OFF_BH);
    bf16* sBl = (bf16*)(smem + OFF_BL);
    uint32_t sbase = smem_to_u32(smem);

    const int t = threadIdx.x, lane = t & 31, wid = t >> 5;
    const int warp_m = wid & 1, warp_n = wid >> 1;   // 2 (M) x 4 (N)
    const int m0 = blockIdx.x * 128;

    if (t < 128) {
        ((float*)(smem + OFF_PAR))[t]       = bias[t];
        ((float*)(smem + OFF_PAR))[128 + t] = gamma[t];
        ((float*)(smem + OFF_PAR))[256 + t] = beta[t];
    }

    float acc[4][4][4];
#pragma unroll
    for (int i = 0; i < 4; ++i)
#pragma unroll
        for (int j = 0; j < 4; ++j)
#pragma unroll
            for (int u = 0; u < 4; ++u) acc[i][j][u] = 0.f;

    const int a_row = warp_m * 64 + (lane & 7) + ((lane >> 3) & 1) * 8;
    const int a_col = (lane >> 4) * 8;
    const int b_row = warp_n * 32 + (lane & 7);
    const int b_col = ((lane >> 3) & 1) * 8;

    for (int k0 = 0; k0 < K; k0 += BK) {
        for (int i = t; i < 2048; i += 256) {
            int row = i >> 4, cq = (i & 15) * 4;
            float4 v = make_float4(0.f, 0.f, 0.f, 0.f);
            int gm = m0 + row;
            if (gm < NN) {
                v = *(const float4*)(A + (size_t)gm * lda + k0 + cq);
                if (rowscale) {
                    float sc = rowscale[gm];
                    v.x *= sc; v.y *= sc; v.z *= sc; v.w *= sc;
                }
            }
            uint2 H, L;
            split2(v.x, v.y, H.x, L.x);
            split2(v.z, v.w, H.y, L.y);
            *(uint2*)(sAh + row * ASTR + cq) = H;
            *(uint2*)(sAl + row * ASTR + cq) = L;
            *(uint2*)(sBh + row * ASTR + cq) = *(const uint2*)(Whi + (size_t)row * K + k0 + cq);
            *(uint2*)(sBl + row * ASTR + cq) = *(const uint2*)(Wlo + (size_t)row * K + k0 + cq);
        }
        __syncthreads();

#pragma unroll
        for (int kk = 0; kk < BK; kk += 16) {
            uint32_t bh[4][2], bl[4][2];
#pragma unroll
            for (int nt = 0; nt < 4; ++nt) {
                uint32_t boff = (uint32_t)(((b_row + nt * 8) * ASTR + kk + b_col) * 2);
                ldsm2(bh[nt], sbase + OFF_BH + boff);
                ldsm2(bl[nt], sbase + OFF_BL + boff);
            }
#pragma unroll
            for (int mt = 0; mt < 4; ++mt) {
                uint32_t ah[4], al[4];
                uint32_t aoff = (uint32_t)(((a_row + mt * 16) * ASTR + kk + a_col) * 2);
                ldsm4(ah, sbase + OFF_AH + aoff);
                ldsm4(al, sbase + OFF_AL + aoff);
#pragma unroll
                for (int nt = 0; nt < 4; ++nt) {
                    mma16816(acc[mt][nt], ah, bh[nt]);
                    mma16816(acc[mt][nt], ah, bl[nt]);
                    mma16816(acc[mt][nt], al, bh[nt]);
                }
            }
        }
        __syncthreads();
    }

    // ---- epilogue in registers ----
    const float* pb = (const float*)(smem + OFF_PAR);
    const float* pg = pb + 128;
    const float* pe = pb + 256;
    float* s_sum = (float*)(smem + OFF_AH);
    float* s_sq  = s_sum + 512;
    float* s_mu  = s_sq + 512;
    float* s_inv = s_mu + 128;

#pragma unroll
    for (int nt = 0; nt < 4; ++nt) {
        int c = warp_n * 32 + nt * 8 + (lane & 3) * 2;
        float b0 = pb[c], b1 = pb[c + 1];
#pragma unroll
        for (int mt = 0; mt < 4; ++mt) {
            acc[mt][nt][0] += b0; acc[mt][nt][1] += b1;
            acc[mt][nt][2] += b0; acc[mt][nt][3] += b1;
        }
    }
#pragma unroll
    for (int mt = 0; mt < 4; ++mt) {
#pragma unroll
        for (int rh = 0; rh < 2; ++rh) {
            float s = 0.f, q = 0.f;
#pragma unroll
            for (int nt = 0; nt < 4; ++nt) {
                float x0 = acc[mt][nt][2 * rh], x1 = acc[mt][nt][2 * rh + 1];
                s += x0 + x1;
                q += x0 * x0 + x1 * x1;
            }
            s += __shfl_xor_sync(0xffffffffu, s, 1);
            q += __shfl_xor_sync(0xffffffffu, q, 1);
            s += __shfl_xor_sync(0xffffffffu, s, 2);
            q += __shfl_xor_sync(0xffffffffu, q, 2);
            if ((lane & 3) == 0) {
                int r = warp_m * 64 + mt * 16 + (lane >> 2) + rh * 8;
                s_sum[warp_n * 128 + r] = s;
                s_sq [warp_n * 128 + r] = q;
            }
        }
    }
    __syncthreads();
    if (t < 128) {
        float s = s_sum[t] + s_sum[128 + t] + s_sum[256 + t] + s_sum[384 + t];
        float q = s_sq [t] + s_sq [128 + t] + s_sq [256 + t] + s_sq [384 + t];
        float mu  = s * (1.0f / 128.0f);
        float var = q * (1.0f / 128.0f) - mu * mu;
        s_mu[t]  = mu;
        s_inv[t] = rsqrtf(var + 1e-5f);
    }
    __syncthreads();
#pragma unroll
    for (int mt = 0; mt < 4; ++mt) {
#pragma unroll
        for (int rh = 0; rh < 2; ++rh) {
            int r = warp_m * 64 + mt * 16 + (lane >> 2) + rh * 8;
            int gm = m0 + r;
            if (gm >= NN) continue;
            float mu = s_mu[r], inv = s_inv[r];
            float* cp = C + (size_t)gm * ldc + noff;
#pragma unroll
            for (int nt = 0; nt < 4; ++nt) {
                int c = warp_n * 32 + nt * 8 + (lane & 3) * 2;
                float2 y;
                y.x = fmaxf((acc[mt][nt][2 * rh]     - mu) * inv * pg[c]     + pe[c],     0.f);
                y.y = fmaxf((acc[mt][nt][2 * rh + 1] - mu) * inv * pg[c + 1] + pe[c + 1], 0.f);
                *(float2*)(cp + c) = y;
            }
        }
    }
}

// ---------------- launch ----------------
extern "C" void kernel_launch(void* const* d_in, const int* in_sizes, int n_in,
                              void* d_out, int out_size)
{
    const void*  ei     = d_in[0];
    const float* feats  = (const float*)d_in[1];
    const float* W_uni  = (const float*)d_in[2];
    const float* b_uni  = (const float*)d_in[3];
    const float* g_uni  = (const float*)d_in[4];
    const float* be_uni = (const float*)d_in[5];
    const float* W_ind  = (const float*)d_in[6];
    const float* b_ind  = (const float*)d_in[7];
    const float* g_ind  = (const float*)d_in[8];
    const float* be_ind = (const float*)d_in[9];
    const float* W_rel  = (const float*)d_in[10];
    const float* b_rel  = (const float*)d_in[11];
    const float* g_rel  = (const float*)d_in[12];
    const float* be_rel = (const float*)d_in[13];
    float* out = (float*)d_out;

    // one-time resource creation (first call = correctness run, pre-baseline).
    static cudaStream_t s2 = nullptr, s3 = nullptr;
    static cudaEvent_t evStart, evW, evH, evZa, evZb, evZc, evDone;
    if (!s2) {
        cudaStreamCreateWithFlags(&s2, cudaStreamNonBlocking);
        cudaStreamCreateWithFlags(&s3, cudaStreamNonBlocking);
        cudaEventCreateWithFlags(&evStart, cudaEventDisableTiming);
        cudaEventCreateWithFlags(&evW,     cudaEventDisableTiming);
        cudaEventCreateWithFlags(&evH,     cudaEventDisableTiming);
        cudaEventCreateWithFlags(&evZa,    cudaEventDisableTiming);
        cudaEventCreateWithFlags(&evZb,    cudaEventDisableTiming);
        cudaEventCreateWithFlags(&evZc,    cudaEventDisableTiming);
        cudaEventCreateWithFlags(&evDone,  cudaEventDisableTiming);
        cudaFuncSetAttribute(k_mma<KIN>, cudaFuncAttributeMaxDynamicSharedMemorySize, SMEM_DYN);
        cudaFuncSetAttribute(k_mma<HF>,  cudaFuncAttributeMaxDynamicSharedMemorySize, SMEM_DYN);
    }

    float *ph, *pza, *pzb, *pzc, *pcat, *pinv;
    bf16 *pwuh, *pwul, *pwih, *pwil, *pwrh, *pwrl;
    cudaGetSymbolAddress((void**)&ph,   g_h);
    cudaGetSymbolAddress((void**)&pza,  g_za);
    cudaGetSymbolAddress((void**)&pzb,  g_zb);
    cudaGetSymbolAddress((void**)&pzc,  g_zc);
    cudaGetSymbolAddress((void**)&pcat, g_cat);
    cudaGetSymbolAddress((void**)&pinv, g_invnorm);
    cudaGetSymbolAddress((void**)&pwuh, g_wu_hi);
    cudaGetSymbolAddress((void**)&pwul, g_wu_lo);
    cudaGetSymbolAddress((void**)&pwih, g_wi_hi);
    cudaGetSymbolAddress((void**)&pwil, g_wi_lo);
    cudaGetSymbolAddress((void**)&pwrh, g_wr_hi);
    cudaGetSymbolAddress((void**)&pwrl, g_wr_lo);

    // fork s2/s3 off the (captured) default stream
    cudaEventRecord(evStart, 0);
    cudaStreamWaitEvent(s2, evStart, 0);
    cudaStreamWaitEvent(s3, evStart, 0);

    // ---- main stream: CSR build chain ----
    k_detect<<<1, 32>>>(ei);
    k_init_cnt<<<(NN + 255) / 256, 256>>>();
    k_count<<<(EE + 255) / 256, 256>>>(ei);
    k_scan1<<<NBLK, 1024>>>();
    k_scan2<<<1, 128>>>();
    k_scan3<<<NBLK, 1024>>>();
    k_scatter<<<(EE + 255) / 256, 256>>>();

    // ---- s3: weight prep (concurrent with invnorm on s2) ----
    k_wprep<<<(HF * KIN + 255) / 256, 256, 0, s3>>>(W_uni, pwuh, pwul, KIN, HF * KIN);
    k_wprep<<<(4 * HF * HF + 255) / 256, 256, 0, s3>>>(W_ind, pwih, pwil, HF, 4 * HF * HF);
    k_wprep<<<(HF * KIN + 255) / 256, 256, 0, s3>>>(W_rel, pwrh, pwrl, KIN, HF * KIN);
    cudaEventRecord(evW, s3);

    // ---- s2: invnorm -> uni GEMM -> hop0 ----
    k_invnorm<<<NN / 8, 256, 0, s2>>>(feats);
    cudaStreamWaitEvent(s2, evW, 0);
    k_mma<KIN><<<GRID_M, 256, SMEM_DYN, s2>>>(feats, KIN, pinv, pwuh, pwul,
                                              b_uni, g_uni, be_uni, ph, HF, 0);
    cudaEventRecord(evH, s2);
    k_mma<HF><<<GRID_M, 256, SMEM_DYN, s2>>>(ph, HF, nullptr, pwih, pwil,
                                             b_ind, g_ind, be_ind, pcat, 4 * HF, 0);

    // ---- main: SpMM chain, overlapped with hop GEMMs on s2 ----
    cudaStreamWaitEvent(0, evH, 0);
    k_spmm<<<NN / 8, 256>>>(ph, pza);
    cudaEventRecord(evZa, 0);
    k_spmm<<<NN / 8, 256>>>(pza, pzb);
    cudaEventRecord(evZb, 0);
    k_spmm<<<NN / 8, 256>>>(pzb, pzc);
    cudaEventRecord(evZc, 0);

    // ---- s2: hop GEMMs as their inputs land ----
    cudaStreamWaitEvent(s2, evZa, 0);
    k_mma<HF><<<GRID_M, 256, SMEM_DYN, s2>>>(pza, HF, nullptr,
                                             pwih + 1 * HF * HF, pwil + 1 * HF * HF,
                                             b_ind + 1 * HF, g_ind + 1 * HF, be_ind + 1 * HF,
                                             pcat, 4 * HF, 1 * HF);
    cudaStreamWaitEvent(s2, evZb, 0);
    k_mma<HF><<<GRID_M, 256, SMEM_DYN, s2>>>(pzb, HF, nullptr,
                                             pwih + 2 * HF * HF, pwil + 2 * HF * HF,
                                             b_ind + 2 * HF, g_ind + 2 * HF, be_ind + 2 * HF,
                                             pcat, 4 * HF, 2 * HF);
    cudaStreamWaitEvent(s2, evZc, 0);
    k_mma<HF><<<GRID_M, 256, SMEM_DYN, s2>>>(pzc, HF, nullptr,
                                             pwih + 3 * HF * HF, pwil + 3 * HF * HF,
                                             b_ind + 3 * HF, g_ind + 3 * HF, be_ind + 3 * HF,
                                             pcat, 4 * HF, 3 * HF);
    // relation MLP -> d_out
    k_mma<KIN><<<GRID_M, 256, SMEM_DYN, s2>>>(pcat, 4 * HF, nullptr, pwrh, pwrl,
                                              b_rel, g_rel, be_rel, out, HF, 0);
    cudaEventRecord(evDone, s2);

    // join
    cudaStreamWaitEvent(0, evDone, 0);
}

// round 9
// speedup vs baseline: 1.8851x; 1.0158x over previous
#include <cuda_runtime.h>
#include <cuda_bf16.h>
#include <cstdint>
#include <cstddef>

#define NN 100000
#define EE 1600000
#define HF 128
#define KIN 512
#define NBLK 98     // ceil(NN/1024)
#define GRID_M 782  // ceil(NN/128)
#define BK 64
#define ASTR 72     // padded smem row stride (bf16 elems)

typedef __nv_bfloat16 bf16;

// ---------------- scratch (static device globals; no allocations) ----------------
__device__ int   g_is64;
__device__ float g_invnorm[NN];
__device__ int   g_cnt[NN];
__device__ float g_dinv[NN];
__device__ int   g_erow[EE];
__device__ int   g_ecol0[EE];
__device__ int   g_off[NN + 1];
__device__ int   g_cursor[NN];
__device__ int   g_bsum[128];
__device__ int   g_boff[128];
__device__ int2  g_epk[EE];          // packed (col, w-bits)

__device__ float g_h  [(size_t)NN * HF];
__device__ float g_za [(size_t)NN * HF];
__device__ float g_zb [(size_t)NN * HF];
__device__ float g_zc [(size_t)NN * HF];
__device__ float g_cat[(size_t)NN * 4 * HF];
__device__ float g_racc[(size_t)NN * HF];

// transposed + hi/lo split weights: Wt[n][k] = W[k][n]
__device__ bf16 g_wu_hi[HF * KIN];
__device__ bf16 g_wu_lo[HF * KIN];
__device__ bf16 g_wi_hi[4 * HF * HF];
__device__ bf16 g_wi_lo[4 * HF * HF];
__device__ bf16 g_wr_hi[HF * KIN];
__device__ bf16 g_wr_lo[HF * KIN];

// ---------------- helpers ----------------
__device__ __forceinline__ uint32_t smem_to_u32(const void* p) {
    uint32_t a;
    asm("{ .reg .u64 t; cvta.to.shared.u64 t, %1; cvt.u32.u64 %0, t; }" : "=r"(a) : "l"(p));
    return a;
}
__device__ __forceinline__ uint32_t bpack(bf16 a, bf16 b) {
    __nv_bfloat162 t(a, b);
    return *reinterpret_cast<uint32_t*>(&t);
}
__device__ __forceinline__ void split2(float a, float b, uint32_t& hi, uint32_t& lo) {
    bf16 ha = __float2bfloat16(a), hb = __float2bfloat16(b);
    float ra = a - __bfloat162float(ha);
    float rb = b - __bfloat162float(hb);
    hi = bpack(ha, hb);
    lo = bpack(__float2bfloat16(ra), __float2bfloat16(rb));
}
__device__ __forceinline__ void ldsm4(uint32_t* r, uint32_t a) {
    asm volatile("ldmatrix.sync.aligned.m8n8.x4.shared.b16 {%0,%1,%2,%3}, [%4];"
        : "=r"(r[0]), "=r"(r[1]), "=r"(r[2]), "=r"(r[3]) : "r"(a));
}
__device__ __forceinline__ void ldsm2(uint32_t* r, uint32_t a) {
    asm volatile("ldmatrix.sync.aligned.m8n8.x2.shared.b16 {%0,%1}, [%2];"
        : "=r"(r[0]), "=r"(r[1]) : "r"(a));
}
__device__ __forceinline__ void mma16816(float* c, const uint32_t* a, const uint32_t* b) {
    asm volatile("mma.sync.aligned.m16n8k16.row.col.f32.bf16.bf16.f32 "
        "{%0,%1,%2,%3}, {%4,%5,%6,%7}, {%8,%9}, {%0,%1,%2,%3};"
        : "+f"(c[0]), "+f"(c[1]), "+f"(c[2]), "+f"(c[3])
        : "r"(a[0]), "r"(a[1]), "r"(a[2]), "r"(a[3]), "r"(b[0]), "r"(b[1]));
}

// ---------------- preprocessing ----------------
__global__ void k_detect(const void* ei) {
    const unsigned int* p = (const unsigned int*)ei;
    int ok64 = 1;
    for (int i = threadIdx.x; i < 64; i += 32)
        if (p[2 * i + 1] != 0u) ok64 = 0;
    ok64 = __all_sync(0xffffffffu, ok64);
    if (threadIdx.x == 0) g_is64 = ok64;
}

__global__ void k_init_cnt() {
    int i = blockIdx.x * blockDim.x + threadIdx.x;
    if (i < NN) g_cnt[i] = 0;
}

__global__ void k_invnorm(const float* __restrict__ feats) {
    int w = (blockIdx.x * blockDim.x + threadIdx.x) >> 5;
    int lane = threadIdx.x & 31;
    if (w >= NN) return;
    const float4* p = (const float4*)(feats + (size_t)w * KIN);
    float ss = 0.f;
#pragma unroll
    for (int i = 0; i < 4; ++i) {
        float4 v = p[i * 32 + lane];
        ss += v.x * v.x + v.y * v.y + v.z * v.z + v.w * v.w;
    }
#pragma unroll
    for (int o = 16; o > 0; o >>= 1) ss += __shfl_xor_sync(0xffffffffu, ss, o);
    if (lane == 0) g_invnorm[w] = 1.0f / fmaxf(sqrtf(ss), 1e-12f);
}

__global__ void k_count(const void* ei) {
    int e = blockIdx.x * blockDim.x + threadIdx.x;
    if (e >= EE) return;
    int r, c;
    if (g_is64) {
        const long long* p = (const long long*)ei;
        r = (int)p[e]; c = (int)p[EE + e];
    } else {
        const int* p = (const int*)ei;
        r = p[e]; c = p[EE + e];
    }
    g_erow[e] = r;
    g_ecol0[e] = c;
    atomicAdd(&g_cnt[r], 1);
}

__global__ void k_scan1() {
    __shared__ int sm[1024];
    int t = threadIdx.x;
    int i = blockIdx.x * 1024 + t;
    int v = (i < NN) ? g_cnt[i] : 0;
    sm[t] = v;
    __syncthreads();
    for (int d = 1; d < 1024; d <<= 1) {
        int add = (t >= d) ? sm[t - d] : 0;
        __syncthreads();
        sm[t] += add;
        __syncthreads();
    }
    int incl = sm[t];
    if (i < NN) g_off[i] = incl - v;
    if (t == 1023) g_bsum[blockIdx.x] = incl;
}

__global__ void k_scan2() {
    __shared__ int sm[128];
    int t = threadIdx.x;
    int v = (t < NBLK) ? g_bsum[t] : 0;
    sm[t] = v;
    __syncthreads();
    for (int d = 1; d < 128; d <<= 1) {
        int add = (t >= d) ? sm[t - d] : 0;
        __syncthreads();
        sm[t] += add;
        __syncthreads();
    }
    g_boff[t] = sm[t] - v;
}

__global__ void k_scan3() {
    int t = threadIdx.x;
    int i = blockIdx.x * 1024 + t;
    if (i < NN) {
        int off = g_off[i] + g_boff[blockIdx.x];
        g_off[i] = off;
        g_cursor[i] = off;
        g_dinv[i] = rsqrtf((float)(g_cnt[i] + 1));
        if (i == 0) g_off[NN] = EE;
    }
}

__global__ void k_scatter() {
    int e = blockIdx.x * blockDim.x + threadIdx.x;
    if (e >= EE) return;
    int r = g_erow[e], c = g_ecol0[e];
    int pos = atomicAdd(&g_cursor[r], 1);
    g_epk[pos] = make_int2(c, __float_as_int(g_dinv[r] * g_dinv[c]));
}

// weight transpose + split: out[m][n][k] = W[m][k][n]
__global__ void k_wprep(const float* __restrict__ W, bf16* __restrict__ hi,
                        bf16* __restrict__ lo, int K, int total) {
    int o = blockIdx.x * blockDim.x + threadIdx.x;
    if (o >= total) return;
    int k = o % K;
    int rem = o / K;
    int n = rem % HF;
    int m = rem / HF;
    float x = W[(size_t)m * K * HF + (size_t)k * HF + n];
    bf16 h = __float2bfloat16(x);
    hi[o] = h;
    lo[o] = __float2bfloat16(x - __bfloat162float(h));
}

// warp-per-node SpMM with self-loop, CSR, register accumulation
__global__ void k_spmm(const float* __restrict__ zin, float* __restrict__ zout) {
    int w = (blockIdx.x * blockDim.x + threadIdx.x) >> 5;
    int lane = threadIdx.x & 31;
    if (w >= NN) return;
    int s = g_off[w], e = g_off[w + 1];
    float dn = g_dinv[w];
    float ws = dn * dn;
    float4 acc = ((const float4*)(zin + (size_t)w * HF))[lane];
    acc.x *= ws; acc.y *= ws; acc.z *= ws; acc.w *= ws;
#pragma unroll 4
    for (int j = s; j < e; ++j) {
        int2 e2 = g_epk[j];
        float wt = __int_as_float(e2.y);
        float4 v = ((const float4*)(zin + (size_t)e2.x * HF))[lane];
        acc.x += wt * v.x; acc.y += wt * v.y; acc.z += wt * v.z; acc.w += wt * v.w;
    }
    ((float4*)(zout + (size_t)w * HF))[lane] = acc;
}

// ---------------- HMMA bf16 3-term GEMM ----------------
// MODE 0: bias+LN+ReLU epilogue -> C
// MODE 1: raw accumulator -> C (fp32, ld=HF), no bias/LN
// MODE 2: add addend[row][c], then bias+LN+ReLU -> C
#define OFF_PAR 0
#define TILE_B  (128 * ASTR * 2)      // 18432
#define OFF_AH  2048
#define OFF_AL  (OFF_AH + TILE_B)
#define OFF_BH  (OFF_AH + 2 * TILE_B)
#define OFF_BL  (OFF_AH + 3 * TILE_B)
#define SMEM_DYN (OFF_AH + 4 * TILE_B)   // 75776

template <int K, int MODE>
__global__ __launch_bounds__(256, 2)
void k_mma(const float* __restrict__ A, int lda, const float* __restrict__ rowscale,
           const bf16* __restrict__ Whi, const bf16* __restrict__ Wlo, int ldb,
           const float* __restrict__ bias, const float* __restrict__ gamma,
           const float* __restrict__ beta,
           const float* __restrict__ addend,
           float* __restrict__ C, int ldc, int noff)
{
    extern __shared__ char smem[];
    bf16* sAh = (bf16*)(smem + OFF_AH);
    bf16* sAl = (bf16*)(smem + OFF_AL);
    bf16* sBh = (bf16*)(smem + OFF_BH);
    bf16* sBl = (bf16*)(smem + OFF_BL);
    uint32_t sbase = smem_to_u32(smem);

    const int t = threadIdx.x, lane = t & 31, wid = t >> 5;
    const int warp_m = wid & 1, warp_n = wid >> 1;   // 2 (M) x 4 (N)
    const int m0 = blockIdx.x * 128;

    if (MODE != 1 && t < 128) {
        ((float*)(smem + OFF_PAR))[t]       = bias[t];
        ((float*)(smem + OFF_PAR))[128 + t] = gamma[t];
        ((float*)(smem + OFF_PAR))[256 + t] = beta[t];
    }

    float acc[4][4][4];
#pragma unroll
    for (int i = 0; i < 4; ++i)
#pragma unroll
        for (int j = 0; j < 4; ++j)
#pragma unroll
            for (int u = 0; u < 4; ++u) acc[i][j][u] = 0.f;

    const int a_row = warp_m * 64 + (lane & 7) + ((lane >> 3) & 1) * 8;
    const int a_col = (lane >> 4) * 8;
    const int b_row = warp_n * 32 + (lane & 7);
    const int b_col = ((lane >> 3) & 1) * 8;

    for (int k0 = 0; k0 < K; k0 += BK) {
        for (int i = t; i < 2048; i += 256) {
            int row = i >> 4, cq = (i & 15) * 4;
            float4 v = make_float4(0.f, 0.f, 0.f, 0.f);
            int gm = m0 + row;
            if (gm < NN) {
                v = *(const float4*)(A + (size_t)gm * lda + k0 + cq);
                if (rowscale) {
                    float sc = rowscale[gm];
                    v.x *= sc; v.y *= sc; v.z *= sc; v.w *= sc;
                }
            }
            uint2 H, L;
            split2(v.x, v.y, H.x, L.x);
            split2(v.z, v.w, H.y, L.y);
            *(uint2*)(sAh + row * ASTR + cq) = H;
            *(uint2*)(sAl + row * ASTR + cq) = L;
            *(uint2*)(sBh + row * ASTR + cq) = *(const uint2*)(Whi + (size_t)row * ldb + k0 + cq);
            *(uint2*)(sBl + row * ASTR + cq) = *(const uint2*)(Wlo + (size_t)row * ldb + k0 + cq);
        }
        __syncthreads();

#pragma unroll
        for (int kk = 0; kk < BK; kk += 16) {
            uint32_t bh[4][2], bl[4][2];
#pragma unroll
            for (int nt = 0; nt < 4; ++nt) {
                uint32_t boff = (uint32_t)(((b_row + nt * 8) * ASTR + kk + b_col) * 2);
                ldsm2(bh[nt], sbase + OFF_BH + boff);
                ldsm2(bl[nt], sbase + OFF_BL + boff);
            }
#pragma unroll
            for (int mt = 0; mt < 4; ++mt) {
                uint32_t ah[4], al[4];
                uint32_t aoff = (uint32_t)(((a_row + mt * 16) * ASTR + kk + a_col) * 2);
                ldsm4(ah, sbase + OFF_AH + aoff);
                ldsm4(al, sbase + OFF_AL + aoff);
#pragma unroll
                for (int nt = 0; nt < 4; ++nt) {
                    mma16816(acc[mt][nt], ah, bh[nt]);
                    mma16816(acc[mt][nt], ah, bl[nt]);
                    mma16816(acc[mt][nt], al, bh[nt]);
                }
            }
        }
        __syncthreads();
    }

    if (MODE == 1) {
        // raw partial accumulator store
#pragma unroll
        for (int mt = 0; mt < 4; ++mt) {
#pragma unroll
            for (int rh = 0; rh < 2; ++rh) {
                int r = warp_m * 64 + mt * 16 + (lane >> 2) + rh * 8;
                int gm = m0 + r;
                if (gm >= NN) continue;
                float* cp = C + (size_t)gm * HF;
#pragma unroll
                for (int nt = 0; nt < 4; ++nt) {
                    int c = warp_n * 32 + nt * 8 + (lane & 3) * 2;
                    *(float2*)(cp + c) = make_float2(acc[mt][nt][2 * rh], acc[mt][nt][2 * rh + 1]);
                }
            }
        }
        return;
    }

    // ---- epilogue in registers (MODE 0 / 2) ----
    const float* pb = (const float*)(smem + OFF_PAR);
    const float* pg = pb + 128;
    const float* pe = pb + 256;
    float* s_sum = (float*)(smem + OFF_AH);
    float* s_sq  = s_sum + 512;
    float* s_mu  = s_sq + 512;
    float* s_inv = s_mu + 128;

#pragma unroll
    for (int mt = 0; mt < 4; ++mt) {
#pragma unroll
        for (int rh = 0; rh < 2; ++rh) {
            int r = warp_m * 64 + mt * 16 + (lane >> 2) + rh * 8;
            int gm = m0 + r;
            const float* ap = (MODE == 2 && gm < NN) ? (addend + (size_t)gm * HF) : nullptr;
            float s = 0.f, q = 0.f;
#pragma unroll
            for (int nt = 0; nt < 4; ++nt) {
                int c = warp_n * 32 + nt * 8 + (lane & 3) * 2;
                float x0 = acc[mt][nt][2 * rh]     + pb[c];
                float x1 = acc[mt][nt][2 * rh + 1] + pb[c + 1];
                if (MODE == 2 && ap) {
                    float2 ad = *(const float2*)(ap + c);
                    x0 += ad.x; x1 += ad.y;
                }
                acc[mt][nt][2 * rh]     = x0;
                acc[mt][nt][2 * rh + 1] = x1;
                s += x0 + x1;
                q += x0 * x0 + x1 * x1;
            }
            s += __shfl_xor_sync(0xffffffffu, s, 1);
            q += __shfl_xor_sync(0xffffffffu, q, 1);
            s += __shfl_xor_sync(0xffffffffu, s, 2);
            q += __shfl_xor_sync(0xffffffffu, q, 2);
            if ((lane & 3) == 0) {
                s_sum[warp_n * 128 + r] = s;
                s_sq [warp_n * 128 + r] = q;
            }
        }
    }
    __syncthreads();
    if (t < 128) {
        float s = s_sum[t] + s_sum[128 + t] + s_sum[256 + t] + s_sum[384 + t];
        float q = s_sq [t] + s_sq [128 + t] + s_sq [256 + t] + s_sq [384 + t];
        float mu  = s * (1.0f / 128.0f);
        float var = q * (1.0f / 128.0f) - mu * mu;
        s_mu[t]  = mu;
        s_inv[t] = rsqrtf(var + 1e-5f);
    }
    __syncthreads();
#pragma unroll
    for (int mt = 0; mt < 4; ++mt) {
#pragma unroll
        for (int rh = 0; rh < 2; ++rh) {
            int r = warp_m * 64 + mt * 16 + (lane >> 2) + rh * 8;
            int gm = m0 + r;
            if (gm >= NN) continue;
            float mu = s_mu[r], inv = s_inv[r];
            float* cp = C + (size_t)gm * ldc + noff;
#pragma unroll
            for (int nt = 0; nt < 4; ++nt) {
                int c = warp_n * 32 + nt * 8 + (lane & 3) * 2;
                float2 y;
                y.x = fmaxf((acc[mt][nt][2 * rh]     - mu) * inv * pg[c]     + pe[c],     0.f);
                y.y = fmaxf((acc[mt][nt][2 * rh + 1] - mu) * inv * pg[c + 1] + pe[c + 1], 0.f);
                *(float2*)(cp + c) = y;
            }
        }
    }
}

// ---------------- launch ----------------
extern "C" void kernel_launch(void* const* d_in, const int* in_sizes, int n_in,
                              void* d_out, int out_size)
{
    const void*  ei     = d_in[0];
    const float* feats  = (const float*)d_in[1];
    const float* W_uni  = (const float*)d_in[2];
    const float* b_uni  = (const float*)d_in[3];
    const float* g_uni  = (const float*)d_in[4];
    const float* be_uni = (const float*)d_in[5];
    const float* W_ind  = (const float*)d_in[6];
    const float* b_ind  = (const float*)d_in[7];
    const float* g_ind  = (const float*)d_in[8];
    const float* be_ind = (const float*)d_in[9];
    const float* W_rel  = (const float*)d_in[10];
    const float* b_rel  = (const float*)d_in[11];
    const float* g_rel  = (const float*)d_in[12];
    const float* be_rel = (const float*)d_in[13];
    float* out = (float*)d_out;

    // one-time resource creation (first call = correctness run, pre-baseline).
    static cudaStream_t s2 = nullptr, s3 = nullptr;
    static cudaEvent_t evStart, evW, evH, evZa, evZb, evZc, evNs1, evR1, evDone;
    if (!s2) {
        cudaStreamCreateWithFlags(&s2, cudaStreamNonBlocking);
        cudaStreamCreateWithFlags(&s3, cudaStreamNonBlocking);
        cudaEventCreateWithFlags(&evStart, cudaEventDisableTiming);
        cudaEventCreateWithFlags(&evW,     cudaEventDisableTiming);
        cudaEventCreateWithFlags(&evH,     cudaEventDisableTiming);
        cudaEventCreateWithFlags(&evZa,    cudaEventDisableTiming);
        cudaEventCreateWithFlags(&evZb,    cudaEventDisableTiming);
        cudaEventCreateWithFlags(&evZc,    cudaEventDisableTiming);
        cudaEventCreateWithFlags(&evNs1,   cudaEventDisableTiming);
        cudaEventCreateWithFlags(&evR1,    cudaEventDisableTiming);
        cudaEventCreateWithFlags(&evDone,  cudaEventDisableTiming);
        cudaFuncSetAttribute(k_mma<KIN, 0>, cudaFuncAttributeMaxDynamicSharedMemorySize, SMEM_DYN);
        cudaFuncSetAttribute(k_mma<HF, 0>,  cudaFuncAttributeMaxDynamicSharedMemorySize, SMEM_DYN);
        cudaFuncSetAttribute(k_mma<256, 1>, cudaFuncAttributeMaxDynamicSharedMemorySize, SMEM_DYN);
        cudaFuncSetAttribute(k_mma<256, 2>, cudaFuncAttributeMaxDynamicSharedMemorySize, SMEM_DYN);
    }

    float *ph, *pza, *pzb, *pzc, *pcat, *pinv, *pracc;
    bf16 *pwuh, *pwul, *pwih, *pwil, *pwrh, *pwrl;
    cudaGetSymbolAddress((void**)&ph,    g_h);
    cudaGetSymbolAddress((void**)&pza,   g_za);
    cudaGetSymbolAddress((void**)&pzb,   g_zb);
    cudaGetSymbolAddress((void**)&pzc,   g_zc);
    cudaGetSymbolAddress((void**)&pcat,  g_cat);
    cudaGetSymbolAddress((void**)&pinv,  g_invnorm);
    cudaGetSymbolAddress((void**)&pracc, g_racc);
    cudaGetSymbolAddress((void**)&pwuh,  g_wu_hi);
    cudaGetSymbolAddress((void**)&pwul,  g_wu_lo);
    cudaGetSymbolAddress((void**)&pwih,  g_wi_hi);
    cudaGetSymbolAddress((void**)&pwil,  g_wi_lo);
    cudaGetSymbolAddress((void**)&pwrh,  g_wr_hi);
    cudaGetSymbolAddress((void**)&pwrl,  g_wr_lo);

    // fork s2/s3 off the (captured) default stream
    cudaEventRecord(evStart, 0);
    cudaStreamWaitEvent(s2, evStart, 0);
    cudaStreamWaitEvent(s3, evStart, 0);

    // ---- main stream: CSR build chain ----
    k_detect<<<1, 32>>>(ei);
    k_init_cnt<<<(NN + 255) / 256, 256>>>();
    k_count<<<(EE + 255) / 256, 256>>>(ei);
    k_scan1<<<NBLK, 1024>>>();
    k_scan2<<<1, 128>>>();
    k_scan3<<<NBLK, 1024>>>();
    k_scatter<<<(EE + 255) / 256, 256>>>();

    // ---- s3: weight prep (concurrent with invnorm on s2) ----
    k_wprep<<<(HF * KIN + 255) / 256, 256, 0, s3>>>(W_uni, pwuh, pwul, KIN, HF * KIN);
    k_wprep<<<(4 * HF * HF + 255) / 256, 256, 0, s3>>>(W_ind, pwih, pwil, HF, 4 * HF * HF);
    k_wprep<<<(HF * KIN + 255) / 256, 256, 0, s3>>>(W_rel, pwrh, pwrl, KIN, HF * KIN);
    cudaEventRecord(evW, s3);

    // ---- s2: invnorm -> uni GEMM -> hop0 ----
    k_invnorm<<<NN / 8, 256, 0, s2>>>(feats);
    cudaStreamWaitEvent(s2, evW, 0);
    k_mma<KIN, 0><<<GRID_M, 256, SMEM_DYN, s2>>>(feats, KIN, pinv, pwuh, pwul, KIN,
                                                 b_uni, g_uni, be_uni, nullptr, ph, HF, 0);
    cudaEventRecord(evH, s2);
    k_mma<HF, 0><<<GRID_M, 256, SMEM_DYN, s2>>>(ph, HF, nullptr, pwih, pwil, HF,
                                                b_ind, g_ind, be_ind, nullptr, pcat, 4 * HF, 0);

    // ---- main: SpMM chain, overlapped with hop GEMMs on s2 ----
    cudaStreamWaitEvent(0, evH, 0);
    k_spmm<<<NN / 8, 256>>>(ph, pza);
    cudaEventRecord(evZa, 0);
    k_spmm<<<NN / 8, 256>>>(pza, pzb);
    cudaEventRecord(evZb, 0);
    k_spmm<<<NN / 8, 256>>>(pzb, pzc);
    cudaEventRecord(evZc, 0);

    // ---- s2: hop GEMMs as their inputs land ----
    cudaStreamWaitEvent(s2, evZa, 0);
    k_mma<HF, 0><<<GRID_M, 256, SMEM_DYN, s2>>>(pza, HF, nullptr,
                                                pwih + 1 * HF * HF, pwil + 1 * HF * HF, HF,
                                                b_ind + 1 * HF, g_ind + 1 * HF, be_ind + 1 * HF,
                                                nullptr, pcat, 4 * HF, 1 * HF);
    cudaEventRecord(evNs1, s2);
    cudaStreamWaitEvent(s2, evZb, 0);
    k_mma<HF, 0><<<GRID_M, 256, SMEM_DYN, s2>>>(pzb, HF, nullptr,
                                                pwih + 2 * HF * HF, pwil + 2 * HF * HF, HF,
                                                b_ind + 2 * HF, g_ind + 2 * HF, be_ind + 2 * HF,
                                                nullptr, pcat, 4 * HF, 2 * HF);
    cudaStreamWaitEvent(s2, evZc, 0);
    k_mma<HF, 0><<<GRID_M, 256, SMEM_DYN, s2>>>(pzc, HF, nullptr,
                                                pwih + 3 * HF * HF, pwil + 3 * HF * HF, HF,
                                                b_ind + 3 * HF, g_ind + 3 * HF, be_ind + 3 * HF,
                                                nullptr, pcat, 4 * HF, 3 * HF);

    // ---- s3: rel half 1 (hops 0-1, cat cols 0..255) -> racc, overlapped w/ spmm2/3 ----
    cudaStreamWaitEvent(s3, evNs1, 0);
    k_mma<256, 1><<<GRID_M, 256, SMEM_DYN, s3>>>(pcat, 4 * HF, nullptr,
                                                 pwrh, pwrl, KIN,
                                                 nullptr, nullptr, nullptr, nullptr,
                                                 pracc, HF, 0);
    cudaEventRecord(evR1, s3);

    // ---- s2 tail: rel half 2 (hops 2-3) + racc + bias + LN + ReLU -> out ----
    cudaStreamWaitEvent(s2, evR1, 0);
    k_mma<256, 2><<<GRID_M, 256, SMEM_DYN, s2>>>(pcat + 256, 4 * HF, nullptr,
                                                 pwrh + 256, pwrl + 256, KIN,
                                                 b_rel, g_rel, be_rel, pracc,
                                                 out, HF, 0);
    cudaEventRecord(evDone, s2);

    // join
    cudaStreamWaitEvent(0, evDone, 0);
}